// round 2
// baseline (speedup 1.0000x reference)
#include <cuda_runtime.h>
#include <math.h>

#define EMB 1024
#define HEADS 16
#define HEAD_SZ 64
#define BT 4096          // B*T
#define FFD 4096
#define N_QKV 3072

// ---------------- scratch (static device arrays; no allocation) ----------------
__device__ float g_h   [BT * EMB];     // 16 MB  LN1 output
__device__ float g_qkv [BT * N_QKV];   // 48 MB  q|k|v packed per row
__device__ float g_o   [BT * EMB];     // 16 MB  attention output (heads concat)
__device__ float g_x1  [BT * EMB];     // 16 MB  x + attn proj
__device__ float g_t   [BT * EMB];     // 16 MB  LN2 pass 1
__device__ float g_t2  [BT * EMB];     // 16 MB  LN2 pass 2
__device__ float g_u   [BT * FFD];     // 64 MB  relu(t@W1+b1)
__device__ float g_wqkv[EMB * N_QKV];  // 12 MB  packed QKV weights [K=1024, N=3072]

// ---------------- pack wq/wk/wv [H, EMB, D] -> row-major [EMB, 3*EMB] ----------
__global__ void pack_qkv_kernel(const float* __restrict__ wq,
                                const float* __restrict__ wk,
                                const float* __restrict__ wv) {
    int idx = blockIdx.x * blockDim.x + threadIdx.x;
    if (idx >= EMB * N_QKV) return;
    int c = idx / N_QKV;
    int n = idx % N_QKV;
    int sel = n >> 10;           // 0=q 1=k 2=v
    int hd  = n & 1023;
    int h = hd >> 6, d = hd & 63;
    const float* w = (sel == 0) ? wq : (sel == 1) ? wk : wv;
    g_wqkv[idx] = w[(size_t)h * EMB * HEAD_SZ + (size_t)c * HEAD_SZ + d];
}

// ---------------- LayerNorm: one block per row of 1024 --------------------------
__global__ __launch_bounds__(256) void ln_kernel(const float* __restrict__ in,
                                                 const float* __restrict__ gw,
                                                 const float* __restrict__ bw,
                                                 float* __restrict__ out) {
    int row = blockIdx.x;
    int tid = threadIdx.x;
    const float4* xr = (const float4*)(in + (size_t)row * EMB);
    float4 xv = xr[tid];
    float s  = xv.x + xv.y + xv.z + xv.w;
    float ss = xv.x*xv.x + xv.y*xv.y + xv.z*xv.z + xv.w*xv.w;
    #pragma unroll
    for (int o = 16; o; o >>= 1) {
        s  += __shfl_xor_sync(0xffffffffu, s,  o);
        ss += __shfl_xor_sync(0xffffffffu, ss, o);
    }
    __shared__ float rs[8], rss[8];
    int wid = tid >> 5, lane = tid & 31;
    if (!lane) { rs[wid] = s; rss[wid] = ss; }
    __syncthreads();
    s = 0.f; ss = 0.f;
    #pragma unroll
    for (int i = 0; i < 8; i++) { s += rs[i]; ss += rss[i]; }
    float mu   = s * (1.0f / EMB);
    float var  = ss * (1.0f / EMB) - mu * mu;
    float rstd = rsqrtf(var + 1e-5f);
    float4 gv = ((const float4*)gw)[tid];
    float4 bv = ((const float4*)bw)[tid];
    float4 ov;
    ov.x = (xv.x - mu) * rstd * gv.x + bv.x;
    ov.y = (xv.y - mu) * rstd * gv.y + bv.y;
    ov.z = (xv.z - mu) * rstd * gv.z + bv.z;
    ov.w = (xv.w - mu) * rstd * gv.w + bv.w;
    ((float4*)(out + (size_t)row * EMB))[tid] = ov;
}

// ---------------- SGEMM: C = A[MxK] @ B[KxN] (+bias)(relu)(+res) ---------------
// 128x128 block tile, BK=8, 256 threads, 8x8 per-thread microtile.
template<bool BIAS, bool RELU, bool RES>
__global__ __launch_bounds__(256) void sgemm_kernel(
    const float* __restrict__ A, const float* __restrict__ Bm,
    const float* __restrict__ bias, const float* __restrict__ res,
    float* __restrict__ C, int M, int N, int K)
{
    __shared__ float As[8][128];
    __shared__ float Bs[8][128];
    int tid = threadIdx.x;
    int m0 = blockIdx.y * 128;
    int n0 = blockIdx.x * 128;
    int ty = tid >> 4, tx = tid & 15;

    int arow = tid >> 1;          // 0..127
    int acol = (tid & 1) * 4;     // 0 / 4
    int brow = tid >> 5;          // 0..7
    int bcol = (tid & 31) * 4;    // 0..124

    const float* Aptr = A + (size_t)(m0 + arow) * K + acol;
    const float* Bptr = Bm + (size_t)brow * N + n0 + bcol;

    float acc[8][8];
    #pragma unroll
    for (int i = 0; i < 8; i++)
        #pragma unroll
        for (int j = 0; j < 8; j++) acc[i][j] = 0.f;

    for (int k0 = 0; k0 < K; k0 += 8) {
        float4 av = *(const float4*)(Aptr + k0);
        As[acol + 0][arow] = av.x;
        As[acol + 1][arow] = av.y;
        As[acol + 2][arow] = av.z;
        As[acol + 3][arow] = av.w;
        float4 bv = *(const float4*)(Bptr + (size_t)k0 * N);
        *(float4*)&Bs[brow][bcol] = bv;
        __syncthreads();
        #pragma unroll
        for (int kk = 0; kk < 8; kk++) {
            float4 a0 = *(const float4*)&As[kk][ty * 8];
            float4 a1 = *(const float4*)&As[kk][ty * 8 + 4];
            float4 b0 = *(const float4*)&Bs[kk][tx * 8];
            float4 b1 = *(const float4*)&Bs[kk][tx * 8 + 4];
            float avr[8] = {a0.x, a0.y, a0.z, a0.w, a1.x, a1.y, a1.z, a1.w};
            float bvr[8] = {b0.x, b0.y, b0.z, b0.w, b1.x, b1.y, b1.z, b1.w};
            #pragma unroll
            for (int i = 0; i < 8; i++)
                #pragma unroll
                for (int j = 0; j < 8; j++)
                    acc[i][j] = fmaf(avr[i], bvr[j], acc[i][j]);
        }
        __syncthreads();
    }

    #pragma unroll
    for (int i = 0; i < 8; i++) {
        int m = m0 + ty * 8 + i;
        #pragma unroll
        for (int j = 0; j < 8; j += 4) {
            int n = n0 + tx * 8 + j;
            float4 cv = make_float4(acc[i][j], acc[i][j+1], acc[i][j+2], acc[i][j+3]);
            if (BIAS) {
                float4 b4 = *(const float4*)(bias + n);
                cv.x += b4.x; cv.y += b4.y; cv.z += b4.z; cv.w += b4.w;
            }
            if (RELU) {
                cv.x = fmaxf(cv.x, 0.f); cv.y = fmaxf(cv.y, 0.f);
                cv.z = fmaxf(cv.z, 0.f); cv.w = fmaxf(cv.w, 0.f);
            }
            if (RES) {
                float4 r4 = *(const float4*)(res + (size_t)m * N + n);
                cv.x += r4.x; cv.y += r4.y; cv.z += r4.z; cv.w += r4.w;
            }
            *(float4*)(C + (size_t)m * N + n) = cv;
        }
    }
}

// ---------------- Flash-style attention --------------------------------------
// grid (8 q-tiles, 16 heads, 4 batch), 256 threads, 128 q-rows x 128 kv-tile.
// Thread (ty,tx): scores 8 rows x 8 cols; output acc 8 rows x 4 dims (dim=tx*4).
#define QLD 132
#define KLD 132
#define VLD 68
#define PLD 132

__global__ __launch_bounds__(256) void attn_kernel() {
    extern __shared__ float smf[];
    float* Qs = smf;                 // [64][QLD]  Qs[d][r]
    float* Ks = Qs + 64 * QLD;       // [64][KLD]  Ks[d][s]
    float* Vs = Ks + 64 * KLD;       // [128][VLD] Vs[s][d]
    float* Ps = Vs + 128 * VLD;      // [128][PLD] probs

    int tid = threadIdx.x;
    int tile = blockIdx.x;           // 0..7
    int h = blockIdx.y;
    int b = blockIdx.z;
    int ty = tid >> 4, tx = tid & 15;
    int t0 = tile * 128;
    int r0 = ty * 8, c0 = tx * 8;

    const float* qbase = g_qkv + (size_t)(b * 1024 + t0) * N_QKV + h * HEAD_SZ;
    const float* kbase = g_qkv + (size_t)(b * 1024) * N_QKV + EMB + h * HEAD_SZ;
    const float* vbase = g_qkv + (size_t)(b * 1024) * N_QKV + 2 * EMB + h * HEAD_SZ;

    // load Q transposed (Qs[d][r])
    #pragma unroll
    for (int i = 0; i < 8; i++) {
        int flat = tid + i * 256;      // 0..2047 over 128 rows * 16 float4
        int r = flat >> 4;
        int dq = (flat & 15) * 4;
        float4 v = *(const float4*)(qbase + (size_t)r * N_QKV + dq);
        Qs[(dq + 0) * QLD + r] = v.x;
        Qs[(dq + 1) * QLD + r] = v.y;
        Qs[(dq + 2) * QLD + r] = v.z;
        Qs[(dq + 3) * QLD + r] = v.w;
    }

    float m_st[8], l_st[8], oacc[8][4];
    #pragma unroll
    for (int i = 0; i < 8; i++) {
        m_st[i] = -INFINITY; l_st[i] = 0.f;
        #pragma unroll
        for (int j = 0; j < 4; j++) oacc[i][j] = 0.f;
    }

    for (int s0 = 0; s0 < 1024; s0 += 128) {
        __syncthreads();   // previous PV done (and Q load done on first iter)
        #pragma unroll
        for (int i = 0; i < 8; i++) {
            int flat = tid + i * 256;
            int r = flat >> 4;
            int dq = (flat & 15) * 4;
            float4 kv = *(const float4*)(kbase + (size_t)(s0 + r) * N_QKV + dq);
            Ks[(dq + 0) * KLD + r] = kv.x;
            Ks[(dq + 1) * KLD + r] = kv.y;
            Ks[(dq + 2) * KLD + r] = kv.z;
            Ks[(dq + 3) * KLD + r] = kv.w;
            float4 vv = *(const float4*)(vbase + (size_t)(s0 + r) * N_QKV + dq);
            *(float4*)&Vs[r * VLD + dq] = vv;
        }
        __syncthreads();

        // ---- scores: 8x8 per thread over d=64 ----
        float sc[8][8];
        #pragma unroll
        for (int i = 0; i < 8; i++)
            #pragma unroll
            for (int j = 0; j < 8; j++) sc[i][j] = 0.f;

        #pragma unroll 4
        for (int d = 0; d < 64; d++) {
            float4 a0 = *(const float4*)&Qs[d * QLD + r0];
            float4 a1 = *(const float4*)&Qs[d * QLD + r0 + 4];
            float4 b0 = *(const float4*)&Ks[d * KLD + c0];
            float4 b1 = *(const float4*)&Ks[d * KLD + c0 + 4];
            float avr[8] = {a0.x, a0.y, a0.z, a0.w, a1.x, a1.y, a1.z, a1.w};
            float bvr[8] = {b0.x, b0.y, b0.z, b0.w, b1.x, b1.y, b1.z, b1.w};
            #pragma unroll
            for (int i = 0; i < 8; i++)
                #pragma unroll
                for (int j = 0; j < 8; j++)
                    sc[i][j] = fmaf(avr[i], bvr[j], sc[i][j]);
        }

        // ---- online softmax (row reduction across 16 tx lanes) ----
        #pragma unroll
        for (int i = 0; i < 8; i++) {
            float mt = -INFINITY;
            #pragma unroll
            for (int j = 0; j < 8; j++) {
                sc[i][j] *= 0.125f;               // 1/sqrt(64)
                mt = fmaxf(mt, sc[i][j]);
            }
            #pragma unroll
            for (int o = 1; o < 16; o <<= 1)
                mt = fmaxf(mt, __shfl_xor_sync(0xffffffffu, mt, o));
            float mnew = fmaxf(m_st[i], mt);
            float alpha = __expf(m_st[i] - mnew);
            float lsum = 0.f;
            #pragma unroll
            for (int j = 0; j < 8; j++) {
                float p = __expf(sc[i][j] - mnew);
                sc[i][j] = p;
                lsum += p;
            }
            #pragma unroll
            for (int o = 1; o < 16; o <<= 1)
                lsum += __shfl_xor_sync(0xffffffffu, lsum, o);
            l_st[i] = l_st[i] * alpha + lsum;
            m_st[i] = mnew;
            #pragma unroll
            for (int j = 0; j < 4; j++) oacc[i][j] *= alpha;
            *(float4*)&Ps[(r0 + i) * PLD + c0]     = make_float4(sc[i][0], sc[i][1], sc[i][2], sc[i][3]);
            *(float4*)&Ps[(r0 + i) * PLD + c0 + 4] = make_float4(sc[i][4], sc[i][5], sc[i][6], sc[i][7]);
        }
        __syncthreads();

        // ---- PV: oacc[8 rows][4 dims] += P[128] @ V[128][4 dims] ----
        int dxo = tx * 4;
        #pragma unroll 2
        for (int s = 0; s < 128; s += 4) {
            float4 v0 = *(const float4*)&Vs[(s + 0) * VLD + dxo];
            float4 v1 = *(const float4*)&Vs[(s + 1) * VLD + dxo];
            float4 v2 = *(const float4*)&Vs[(s + 2) * VLD + dxo];
            float4 v3 = *(const float4*)&Vs[(s + 3) * VLD + dxo];
            #pragma unroll
            for (int i = 0; i < 8; i++) {
                float4 p4 = *(const float4*)&Ps[(r0 + i) * PLD + s];
                oacc[i][0] = fmaf(p4.x, v0.x, oacc[i][0]);
                oacc[i][1] = fmaf(p4.x, v0.y, oacc[i][1]);
                oacc[i][2] = fmaf(p4.x, v0.z, oacc[i][2]);
                oacc[i][3] = fmaf(p4.x, v0.w, oacc[i][3]);
                oacc[i][0] = fmaf(p4.y, v1.x, oacc[i][0]);
                oacc[i][1] = fmaf(p4.y, v1.y, oacc[i][1]);
                oacc[i][2] = fmaf(p4.y, v1.z, oacc[i][2]);
                oacc[i][3] = fmaf(p4.y, v1.w, oacc[i][3]);
                oacc[i][0] = fmaf(p4.z, v2.x, oacc[i][0]);
                oacc[i][1] = fmaf(p4.z, v2.y, oacc[i][1]);
                oacc[i][2] = fmaf(p4.z, v2.z, oacc[i][2]);
                oacc[i][3] = fmaf(p4.z, v2.w, oacc[i][3]);
                oacc[i][0] = fmaf(p4.w, v3.x, oacc[i][0]);
                oacc[i][1] = fmaf(p4.w, v3.y, oacc[i][1]);
                oacc[i][2] = fmaf(p4.w, v3.z, oacc[i][2]);
                oacc[i][3] = fmaf(p4.w, v3.w, oacc[i][3]);
            }
        }
    }

    // ---- write output: o[b, t, h*64 + d] ----
    float* obase = g_o + (size_t)(b * 1024 + t0) * EMB + h * HEAD_SZ;
    #pragma unroll
    for (int i = 0; i < 8; i++) {
        float inv = 1.0f / l_st[i];
        float4 ov = make_float4(oacc[i][0] * inv, oacc[i][1] * inv,
                                oacc[i][2] * inv, oacc[i][3] * inv);
        *(float4*)(obase + (size_t)(ty * 8 + i) * EMB + tx * 4) = ov;
    }
}

// ---------------- launch --------------------------------------------------------
extern "C" void kernel_launch(void* const* d_in, const int* in_sizes, int n_in,
                              void* d_out, int out_size) {
    const float* x      = (const float*)d_in[0];
    const float* wq     = (const float*)d_in[1];
    const float* wk     = (const float*)d_in[2];
    const float* wv     = (const float*)d_in[3];
    const float* w_proj = (const float*)d_in[4];
    const float* b_proj = (const float*)d_in[5];
    const float* w1     = (const float*)d_in[6];
    const float* b1     = (const float*)d_in[7];
    const float* w2     = (const float*)d_in[8];
    const float* b2     = (const float*)d_in[9];
    const float* g1     = (const float*)d_in[10];
    const float* be1    = (const float*)d_in[11];
    const float* g2     = (const float*)d_in[12];
    const float* be2    = (const float*)d_in[13];
    float* out = (float*)d_out;

    float *ph, *pqkv, *po, *px1, *pt, *pt2, *pu, *pw;
    cudaGetSymbolAddress((void**)&ph,   g_h);
    cudaGetSymbolAddress((void**)&pqkv, g_qkv);
    cudaGetSymbolAddress((void**)&po,   g_o);
    cudaGetSymbolAddress((void**)&px1,  g_x1);
    cudaGetSymbolAddress((void**)&pt,   g_t);
    cudaGetSymbolAddress((void**)&pt2,  g_t2);
    cudaGetSymbolAddress((void**)&pu,   g_u);
    cudaGetSymbolAddress((void**)&pw,   g_wqkv);

    // 1. pack QKV weights
    pack_qkv_kernel<<<(EMB * N_QKV + 255) / 256, 256>>>(wq, wk, wv);
    // 2. h = LN(x, g1, be1)
    ln_kernel<<<BT, 256>>>(x, g1, be1, ph);
    // 3. qkv = h @ Wqkv  [4096 x 3072]
    sgemm_kernel<false, false, false><<<dim3(N_QKV / 128, BT / 128), 256>>>(
        ph, pw, nullptr, nullptr, pqkv, BT, N_QKV, EMB);
    // 4. attention
    int smem = (64 * QLD + 64 * KLD + 128 * VLD + 128 * PLD) * (int)sizeof(float);
    cudaFuncSetAttribute(attn_kernel, cudaFuncAttributeMaxDynamicSharedMemorySize, smem);
    attn_kernel<<<dim3(8, HEADS, 4), 256, smem>>>();
    // 5. x1 = x + o @ Wproj + bproj
    sgemm_kernel<true, false, true><<<dim3(EMB / 128, BT / 128), 256>>>(
        po, w_proj, b_proj, x, px1, BT, EMB, EMB);
    // 6. t = LN(LN(x1))  (faithful double LN)
    ln_kernel<<<BT, 256>>>(px1, g2, be2, pt);
    ln_kernel<<<BT, 256>>>(pt, g2, be2, pt2);
    // 7. u = relu(t @ W1 + b1)
    sgemm_kernel<true, true, false><<<dim3(FFD / 128, BT / 128), 256>>>(
        pt2, w1, b1, nullptr, pu, BT, FFD, EMB);
    // 8. out = x1 + u @ W2 + b2
    sgemm_kernel<true, false, true><<<dim3(EMB / 128, BT / 128), 256>>>(
        pu, w2, b2, px1, out, BT, EMB, FFD);
}

// round 6
// speedup vs baseline: 2.3277x; 2.3277x over previous
#include <cuda_runtime.h>
#include <cuda_bf16.h>
#include <math.h>
#include <stdint.h>

#define EMB 1024
#define HEADS 16
#define HEAD_SZ 64
#define BT 4096
#define FFD 4096
#define N_QKV 3072

// ---------------- scratch (static device arrays; no allocation) ----------------
__device__ float g_qkv [BT * N_QKV];            // 48 MB
__device__ float g_x1  [BT * EMB];              // 16 MB
__device__ float g_t   [BT * EMB];              // 16 MB (LN2 pass-1 fp32)
__device__ __nv_bfloat16 g_ah[BT * EMB];        // 8 MB  activation hi (K<=1024 GEMMs)
__device__ __nv_bfloat16 g_al[BT * EMB];        // 8 MB  activation lo
__device__ __nv_bfloat16 g_uh[BT * FFD];        // 32 MB FF hidden hi
__device__ __nv_bfloat16 g_ul[BT * FFD];        // 32 MB FF hidden lo
// bf16 hi/lo transposed weights, Bt[N][K] layout (K contiguous)
__device__ __nv_bfloat16 g_wqkv_h[N_QKV * EMB];
__device__ __nv_bfloat16 g_wqkv_l[N_QKV * EMB];
__device__ __nv_bfloat16 g_wp_h  [EMB * EMB];
__device__ __nv_bfloat16 g_wp_l  [EMB * EMB];
__device__ __nv_bfloat16 g_w1_h  [FFD * EMB];
__device__ __nv_bfloat16 g_w1_l  [FFD * EMB];
__device__ __nv_bfloat16 g_w2_h  [EMB * FFD];
__device__ __nv_bfloat16 g_w2_l  [EMB * FFD];

// ================= helpers =================
__device__ __forceinline__ uint32_t smem_u32(const void* p) {
    uint32_t a;
    asm("{ .reg .u64 t; cvta.to.shared.u64 t, %1; cvt.u32.u64 %0, t; }" : "=r"(a) : "l"(p));
    return a;
}
__device__ __forceinline__ void ldsm4(uint32_t& a, uint32_t& b, uint32_t& c, uint32_t& d,
                                      uint32_t addr) {
    asm volatile("ldmatrix.sync.aligned.m8n8.x4.shared.b16 {%0,%1,%2,%3}, [%4];"
                 : "=r"(a), "=r"(b), "=r"(c), "=r"(d) : "r"(addr));
}
__device__ __forceinline__ void mma_bf16(float* c, const uint32_t* a, const uint32_t* b) {
    asm volatile("mma.sync.aligned.m16n8k16.row.col.f32.bf16.bf16.f32 "
                 "{%0,%1,%2,%3}, {%4,%5,%6,%7}, {%8,%9}, {%0,%1,%2,%3};"
                 : "+f"(c[0]), "+f"(c[1]), "+f"(c[2]), "+f"(c[3])
                 : "r"(a[0]), "r"(a[1]), "r"(a[2]), "r"(a[3]), "r"(b[0]), "r"(b[1]));
}
__device__ __forceinline__ void cp_async16(uint32_t dst, const void* src) {
    asm volatile("cp.async.cg.shared.global [%0], [%1], 16;" :: "r"(dst), "l"(src));
}
#define CP_COMMIT() asm volatile("cp.async.commit_group;" ::: "memory")

__device__ __forceinline__ void split1(float v, __nv_bfloat16& h, __nv_bfloat16& l) {
    h = __float2bfloat16(v);
    l = __float2bfloat16(v - __bfloat162float(h));
}

// ================= weight prep kernels =================
// tiled transpose+split: W[K,N] -> Wt[N,K] hi/lo. block (32,8), grid (N/32, K/32)
__global__ void tsplit_w_tiled(const float* __restrict__ W,
                               __nv_bfloat16* __restrict__ oh,
                               __nv_bfloat16* __restrict__ ol, int K, int N) {
    __shared__ float tile[32][33];
    int nb = blockIdx.x * 32, kb = blockIdx.y * 32;
    int tx = threadIdx.x, ty = threadIdx.y;
    #pragma unroll
    for (int i = 0; i < 4; i++)
        tile[ty + i * 8][tx] = W[(size_t)(kb + ty + i * 8) * N + nb + tx];
    __syncthreads();
    #pragma unroll
    for (int i = 0; i < 4; i++) {
        float v = tile[tx][ty + i * 8];
        __nv_bfloat16 hh, ll; split1(v, hh, ll);
        size_t o = (size_t)(nb + ty + i * 8) * K + kb + tx;
        oh[o] = hh; ol[o] = ll;
    }
}

// pack+transpose+split qkv: w[h][c][d] -> Bt[n=sel*1024+h*64+d][k=c]
// block (32,8), grid (EMB/32, 64/32, 3*16)
__global__ void pack_qkv_tiled(const float* __restrict__ wq,
                               const float* __restrict__ wk,
                               const float* __restrict__ wv) {
    __shared__ float tile[32][33];
    int hz = blockIdx.z;
    int sel = hz >> 4, h = hz & 15;
    const float* w = (sel == 0) ? wq : (sel == 1) ? wk : wv;
    int c0 = blockIdx.x * 32, d0 = blockIdx.y * 32;
    int tx = threadIdx.x, ty = threadIdx.y;
    const float* base = w + (size_t)h * EMB * HEAD_SZ;
    #pragma unroll
    for (int i = 0; i < 4; i++)
        tile[ty + i * 8][tx] = base[(size_t)(c0 + ty + i * 8) * HEAD_SZ + d0 + tx];
    __syncthreads();
    #pragma unroll
    for (int i = 0; i < 4; i++) {
        float v = tile[tx][ty + i * 8];
        __nv_bfloat16 hh, ll; split1(v, hh, ll);
        size_t n = (size_t)sel * 1024 + h * 64 + d0 + ty + i * 8;
        g_wqkv_h[n * EMB + c0 + tx] = hh;
        g_wqkv_l[n * EMB + c0 + tx] = ll;
    }
}

// ================= LayerNorm variants =================
__device__ __forceinline__ void ln_stats(float4 xv, int tid, float& mu, float& rstd) {
    float s  = xv.x + xv.y + xv.z + xv.w;
    float ss = xv.x*xv.x + xv.y*xv.y + xv.z*xv.z + xv.w*xv.w;
    #pragma unroll
    for (int o = 16; o; o >>= 1) {
        s  += __shfl_xor_sync(0xffffffffu, s,  o);
        ss += __shfl_xor_sync(0xffffffffu, ss, o);
    }
    __shared__ float rs[8], rss[8];
    int wid = tid >> 5, lane = tid & 31;
    if (!lane) { rs[wid] = s; rss[wid] = ss; }
    __syncthreads();
    s = 0.f; ss = 0.f;
    #pragma unroll
    for (int i = 0; i < 8; i++) { s += rs[i]; ss += rss[i]; }
    mu = s * (1.0f / EMB);
    float var = ss * (1.0f / EMB) - mu * mu;
    rstd = rsqrtf(var + 1e-5f);
}

// LN with fp32 output (for LN2 pass 1)
__global__ __launch_bounds__(256) void ln_kernel(const float* __restrict__ in,
                                                 const float* __restrict__ gw,
                                                 const float* __restrict__ bw,
                                                 float* __restrict__ out) {
    int row = blockIdx.x;
    int tid = threadIdx.x;
    float4 xv = ((const float4*)(in + (size_t)row * EMB))[tid];
    float mu, rstd;
    ln_stats(xv, tid, mu, rstd);
    float4 gv = ((const float4*)gw)[tid];
    float4 bv = ((const float4*)bw)[tid];
    float4 ov;
    ov.x = (xv.x - mu) * rstd * gv.x + bv.x;
    ov.y = (xv.y - mu) * rstd * gv.y + bv.y;
    ov.z = (xv.z - mu) * rstd * gv.z + bv.z;
    ov.w = (xv.w - mu) * rstd * gv.w + bv.w;
    ((float4*)(out + (size_t)row * EMB))[tid] = ov;
}

// LN with fused bf16 hi/lo split output
__global__ __launch_bounds__(256) void ln_split_kernel(const float* __restrict__ in,
                                                       const float* __restrict__ gw,
                                                       const float* __restrict__ bw,
                                                       __nv_bfloat16* __restrict__ oh,
                                                       __nv_bfloat16* __restrict__ ol) {
    int row = blockIdx.x;
    int tid = threadIdx.x;
    float4 xv = ((const float4*)(in + (size_t)row * EMB))[tid];
    float mu, rstd;
    ln_stats(xv, tid, mu, rstd);
    float4 gv = ((const float4*)gw)[tid];
    float4 bv = ((const float4*)bw)[tid];
    float o[4];
    o[0] = (xv.x - mu) * rstd * gv.x + bv.x;
    o[1] = (xv.y - mu) * rstd * gv.y + bv.y;
    o[2] = (xv.z - mu) * rstd * gv.z + bv.z;
    o[3] = (xv.w - mu) * rstd * gv.w + bv.w;
    __nv_bfloat16 h[4], l[4];
    #pragma unroll
    for (int j = 0; j < 4; j++) split1(o[j], h[j], l[j]);
    *(uint2*)(oh + (size_t)row * EMB + tid * 4) = *(const uint2*)h;
    *(uint2*)(ol + (size_t)row * EMB + tid * 4) = *(const uint2*)l;
}

// ================= mma.sync GEMM (bf16x3 fp32 emulation) =================
// C[M,N] = A[M,K] @ Bt[N,K]^T. CTA 128x128, BK=64, double-buffered cp.async.
// 8 warps: warp tile 64(m) x 32(n). 128B-row XOR swizzle in smem.
#define GT 16384                 // one 128x64 bf16 tile
#define GSTAGE (4 * GT)          // Ah, Al, Bh, Bl
#define G_SMEM (2 * GSTAGE)      // 128 KB

template<bool BIAS, bool RELU, bool RES, bool OSPLIT>
__global__ __launch_bounds__(256, 1) void gemm_mma_kernel(
    const __nv_bfloat16* __restrict__ Ah, const __nv_bfloat16* __restrict__ Al,
    const __nv_bfloat16* __restrict__ Bh, const __nv_bfloat16* __restrict__ Bl,
    const float* __restrict__ bias, const float* __restrict__ res,
    float* __restrict__ C,
    __nv_bfloat16* __restrict__ Oh, __nv_bfloat16* __restrict__ Ol,
    int M, int N, int K)
{
    extern __shared__ __align__(1024) char smem[];
    int tid = threadIdx.x, lane = tid & 31, wid = tid >> 5;
    int m0 = blockIdx.y * 128, n0 = blockIdx.x * 128;
    int wm = (wid >> 2) * 64, wn = (wid & 3) * 32;

    const __nv_bfloat16* srcs[4] = {Ah + (size_t)m0 * K, Al + (size_t)m0 * K,
                                    Bh + (size_t)n0 * K, Bl + (size_t)n0 * K};
    int fr[4], fc[4];
    #pragma unroll
    for (int i = 0; i < 4; i++) {
        int flat = i * 256 + tid;
        fr[i] = flat >> 3;
        fc[i] = flat & 7;
    }

    int nst = K >> 6;

    {   // prologue: stage 0
        char* buf = smem;
        #pragma unroll
        for (int t = 0; t < 4; t++)
            #pragma unroll
            for (int i = 0; i < 4; i++) {
                uint32_t sw = fr[i] * 128 + ((fc[i] ^ (fr[i] & 7)) * 16);
                cp_async16(smem_u32(buf + t * GT + sw),
                           srcs[t] + (size_t)fr[i] * K + fc[i] * 8);
            }
        CP_COMMIT();
    }

    float acc[4][4][4];
    #pragma unroll
    for (int i = 0; i < 4; i++)
        #pragma unroll
        for (int j = 0; j < 4; j++)
            #pragma unroll
            for (int r = 0; r < 4; r++) acc[i][j][r] = 0.f;

    for (int kt = 0; kt < nst; kt++) {
        if (kt + 1 < nst) {
            char* buf = smem + ((kt + 1) & 1) * GSTAGE;
            int ko = (kt + 1) * 64;
            #pragma unroll
            for (int t = 0; t < 4; t++)
                #pragma unroll
                for (int i = 0; i < 4; i++) {
                    uint32_t sw = fr[i] * 128 + ((fc[i] ^ (fr[i] & 7)) * 16);
                    cp_async16(smem_u32(buf + t * GT + sw),
                               srcs[t] + (size_t)fr[i] * K + ko + fc[i] * 8);
                }
            CP_COMMIT();
            asm volatile("cp.async.wait_group 1;" ::: "memory");
        } else {
            asm volatile("cp.async.wait_group 0;" ::: "memory");
        }
        __syncthreads();

        char* buf = smem + (kt & 1) * GSTAGE;
        uint32_t aH = smem_u32(buf);
        uint32_t aL = aH + GT, bH = aH + 2 * GT, bL = aH + 3 * GT;

        #pragma unroll
        for (int kk = 0; kk < 4; kk++) {
            uint32_t ah[4][4], al[4][4];
            #pragma unroll
            for (int i = 0; i < 4; i++) {
                int arow = wm + i * 16 + (lane & 15);
                uint32_t off = arow * 128 + (((kk * 2 + (lane >> 4)) ^ (arow & 7)) * 16);
                ldsm4(ah[i][0], ah[i][1], ah[i][2], ah[i][3], aH + off);
                ldsm4(al[i][0], al[i][1], al[i][2], al[i][3], aL + off);
            }
            uint32_t bh[4][2], bl[4][2];
            #pragma unroll
            for (int jp = 0; jp < 2; jp++) {
                int brow = wn + (jp * 2 + (lane >> 4)) * 8 + (lane & 7);
                int sub = (lane >> 3) & 1;
                uint32_t off = brow * 128 + (((kk * 2 + sub) ^ (brow & 7)) * 16);
                uint32_t r0, r1, r2, r3;
                ldsm4(r0, r1, r2, r3, bH + off);
                bh[jp * 2][0] = r0; bh[jp * 2][1] = r1;
                bh[jp * 2 + 1][0] = r2; bh[jp * 2 + 1][1] = r3;
                ldsm4(r0, r1, r2, r3, bL + off);
                bl[jp * 2][0] = r0; bl[jp * 2][1] = r1;
                bl[jp * 2 + 1][0] = r2; bl[jp * 2 + 1][1] = r3;
            }
            #pragma unroll
            for (int i = 0; i < 4; i++)
                #pragma unroll
                for (int j = 0; j < 4; j++) {
                    mma_bf16(acc[i][j], ah[i], bh[j]);
                    mma_bf16(acc[i][j], ah[i], bl[j]);
                    mma_bf16(acc[i][j], al[i], bh[j]);
                }
        }
        __syncthreads();
    }

    // epilogue
    int r_lo = lane >> 2, c_lo = (lane & 3) * 2;
    #pragma unroll
    for (int i = 0; i < 4; i++)
        #pragma unroll
        for (int rr = 0; rr < 2; rr++) {
            int m = m0 + wm + i * 16 + r_lo + rr * 8;
            const float* rrow = RES ? (res + (size_t)m * N) : (const float*)0;
            #pragma unroll
            for (int j = 0; j < 4; j++) {
                int n = n0 + wn + j * 8 + c_lo;
                float2 v = make_float2(acc[i][j][rr * 2], acc[i][j][rr * 2 + 1]);
                if (BIAS) {
                    float2 b2v = *(const float2*)(bias + n);
                    v.x += b2v.x; v.y += b2v.y;
                }
                if (RELU) { v.x = fmaxf(v.x, 0.f); v.y = fmaxf(v.y, 0.f); }
                if (RES) {
                    float2 r2v = *(const float2*)(rrow + n);
                    v.x += r2v.x; v.y += r2v.y;
                }
                if (OSPLIT) {
                    __nv_bfloat16 hx, lx, hy, ly;
                    split1(v.x, hx, lx);
                    split1(v.y, hy, ly);
                    __nv_bfloat162 hp, lp;
                    hp.x = hx; hp.y = hy;
                    lp.x = lx; lp.y = ly;
                    *(__nv_bfloat162*)(Oh + (size_t)m * N + n) = hp;
                    *(__nv_bfloat162*)(Ol + (size_t)m * N + n) = lp;
                } else {
                    *(float2*)(C + (size_t)m * N + n) = v;
                }
            }
        }
}

// ================= Flash-style attention (SIMT fp32, split-output) =================
#define QLD 132
#define KLD 132
#define VLD 68
#define PLD 132

__global__ __launch_bounds__(256) void attn_kernel() {
    extern __shared__ float smf[];
    float* Qs = smf;
    float* Ks = Qs + 64 * QLD;
    float* Vs = Ks + 64 * KLD;
    float* Ps = Vs + 128 * VLD;

    int tid = threadIdx.x;
    int tile = blockIdx.x;
    int h = blockIdx.y;
    int b = blockIdx.z;
    int ty = tid >> 4, tx = tid & 15;
    int t0 = tile * 128;
    int r0 = ty * 8, c0 = tx * 8;

    const float* qbase = g_qkv + (size_t)(b * 1024 + t0) * N_QKV + h * HEAD_SZ;
    const float* kbase = g_qkv + (size_t)(b * 1024) * N_QKV + EMB + h * HEAD_SZ;
    const float* vbase = g_qkv + (size_t)(b * 1024) * N_QKV + 2 * EMB + h * HEAD_SZ;

    #pragma unroll
    for (int i = 0; i < 8; i++) {
        int flat = tid + i * 256;
        int r = flat >> 4;
        int dq = (flat & 15) * 4;
        float4 v = *(const float4*)(qbase + (size_t)r * N_QKV + dq);
        Qs[(dq + 0) * QLD + r] = v.x;
        Qs[(dq + 1) * QLD + r] = v.y;
        Qs[(dq + 2) * QLD + r] = v.z;
        Qs[(dq + 3) * QLD + r] = v.w;
    }

    float m_st[8], l_st[8], oacc[8][4];
    #pragma unroll
    for (int i = 0; i < 8; i++) {
        m_st[i] = -INFINITY; l_st[i] = 0.f;
        #pragma unroll
        for (int j = 0; j < 4; j++) oacc[i][j] = 0.f;
    }

    for (int s0 = 0; s0 < 1024; s0 += 128) {
        __syncthreads();
        #pragma unroll
        for (int i = 0; i < 8; i++) {
            int flat = tid + i * 256;
            int r = flat >> 4;
            int dq = (flat & 15) * 4;
            float4 kv = *(const float4*)(kbase + (size_t)(s0 + r) * N_QKV + dq);
            Ks[(dq + 0) * KLD + r] = kv.x;
            Ks[(dq + 1) * KLD + r] = kv.y;
            Ks[(dq + 2) * KLD + r] = kv.z;
            Ks[(dq + 3) * KLD + r] = kv.w;
            float4 vv = *(const float4*)(vbase + (size_t)(s0 + r) * N_QKV + dq);
            *(float4*)&Vs[r * VLD + dq] = vv;
        }
        __syncthreads();

        float sc[8][8];
        #pragma unroll
        for (int i = 0; i < 8; i++)
            #pragma unroll
            for (int j = 0; j < 8; j++) sc[i][j] = 0.f;

        #pragma unroll 4
        for (int d = 0; d < 64; d++) {
            float4 a0 = *(const float4*)&Qs[d * QLD + r0];
            float4 a1 = *(const float4*)&Qs[d * QLD + r0 + 4];
            float4 b0 = *(const float4*)&Ks[d * KLD + c0];
            float4 b1 = *(const float4*)&Ks[d * KLD + c0 + 4];
            float avr[8] = {a0.x, a0.y, a0.z, a0.w, a1.x, a1.y, a1.z, a1.w};
            float bvr[8] = {b0.x, b0.y, b0.z, b0.w, b1.x, b1.y, b1.z, b1.w};
            #pragma unroll
            for (int i = 0; i < 8; i++)
                #pragma unroll
                for (int j = 0; j < 8; j++)
                    sc[i][j] = fmaf(avr[i], bvr[j], sc[i][j]);
        }

        #pragma unroll
        for (int i = 0; i < 8; i++) {
            float mt = -INFINITY;
            #pragma unroll
            for (int j = 0; j < 8; j++) {
                sc[i][j] *= 0.125f;
                mt = fmaxf(mt, sc[i][j]);
            }
            #pragma unroll
            for (int o = 1; o < 16; o <<= 1)
                mt = fmaxf(mt, __shfl_xor_sync(0xffffffffu, mt, o));
            float mnew = fmaxf(m_st[i], mt);
            float alpha = __expf(m_st[i] - mnew);
            float lsum = 0.f;
            #pragma unroll
            for (int j = 0; j < 8; j++) {
                float p = __expf(sc[i][j] - mnew);
                sc[i][j] = p;
                lsum += p;
            }
            #pragma unroll
            for (int o = 1; o < 16; o <<= 1)
                lsum += __shfl_xor_sync(0xffffffffu, lsum, o);
            l_st[i] = l_st[i] * alpha + lsum;
            m_st[i] = mnew;
            #pragma unroll
            for (int j = 0; j < 4; j++) oacc[i][j] *= alpha;
            *(float4*)&Ps[(r0 + i) * PLD + c0]     = make_float4(sc[i][0], sc[i][1], sc[i][2], sc[i][3]);
            *(float4*)&Ps[(r0 + i) * PLD + c0 + 4] = make_float4(sc[i][4], sc[i][5], sc[i][6], sc[i][7]);
        }
        __syncthreads();

        int dxo = tx * 4;
        #pragma unroll 2
        for (int s = 0; s < 128; s += 4) {
            float4 v0 = *(const float4*)&Vs[(s + 0) * VLD + dxo];
            float4 v1 = *(const float4*)&Vs[(s + 1) * VLD + dxo];
            float4 v2 = *(const float4*)&Vs[(s + 2) * VLD + dxo];
            float4 v3 = *(const float4*)&Vs[(s + 3) * VLD + dxo];
            #pragma unroll
            for (int i = 0; i < 8; i++) {
                float4 p4 = *(const float4*)&Ps[(r0 + i) * PLD + s];
                oacc[i][0] = fmaf(p4.x, v0.x, oacc[i][0]);
                oacc[i][1] = fmaf(p4.x, v0.y, oacc[i][1]);
                oacc[i][2] = fmaf(p4.x, v0.z, oacc[i][2]);
                oacc[i][3] = fmaf(p4.x, v0.w, oacc[i][3]);
                oacc[i][0] = fmaf(p4.y, v1.x, oacc[i][0]);
                oacc[i][1] = fmaf(p4.y, v1.y, oacc[i][1]);
                oacc[i][2] = fmaf(p4.y, v1.z, oacc[i][2]);
                oacc[i][3] = fmaf(p4.y, v1.w, oacc[i][3]);
                oacc[i][0] = fmaf(p4.z, v2.x, oacc[i][0]);
                oacc[i][1] = fmaf(p4.z, v2.y, oacc[i][1]);
                oacc[i][2] = fmaf(p4.z, v2.z, oacc[i][2]);
                oacc[i][3] = fmaf(p4.z, v2.w, oacc[i][3]);
                oacc[i][0] = fmaf(p4.w, v3.x, oacc[i][0]);
                oacc[i][1] = fmaf(p4.w, v3.y, oacc[i][1]);
                oacc[i][2] = fmaf(p4.w, v3.z, oacc[i][2]);
                oacc[i][3] = fmaf(p4.w, v3.w, oacc[i][3]);
            }
        }
    }

    // write pre-split bf16 hi/lo output: o[b, t, h*64 + d]
    size_t obase = (size_t)(b * 1024 + t0) * EMB + h * HEAD_SZ;
    #pragma unroll
    for (int i = 0; i < 8; i++) {
        float inv = 1.0f / l_st[i];
        __nv_bfloat16 hv[4], lv[4];
        #pragma unroll
        for (int j = 0; j < 4; j++) split1(oacc[i][j] * inv, hv[j], lv[j]);
        size_t off = obase + (size_t)(ty * 8 + i) * EMB + tx * 4;
        *(uint2*)(g_ah + off) = *(const uint2*)hv;
        *(uint2*)(g_al + off) = *(const uint2*)lv;
    }
}

// ================= launch =================
extern "C" void kernel_launch(void* const* d_in, const int* in_sizes, int n_in,
                              void* d_out, int out_size) {
    const float* x      = (const float*)d_in[0];
    const float* wq     = (const float*)d_in[1];
    const float* wk     = (const float*)d_in[2];
    const float* wv     = (const float*)d_in[3];
    const float* w_proj = (const float*)d_in[4];
    const float* b_proj = (const float*)d_in[5];
    const float* w1     = (const float*)d_in[6];
    const float* b1     = (const float*)d_in[7];
    const float* w2     = (const float*)d_in[8];
    const float* b2     = (const float*)d_in[9];
    const float* g1     = (const float*)d_in[10];
    const float* be1    = (const float*)d_in[11];
    const float* g2     = (const float*)d_in[12];
    const float* be2    = (const float*)d_in[13];
    float* out = (float*)d_out;

    float *pqkv, *px1, *pt;
    __nv_bfloat16 *pah, *pal, *puh, *pul, *pwqh, *pwql, *pwph, *pwpl, *pw1h, *pw1l, *pw2h, *pw2l;
    cudaGetSymbolAddress((void**)&pqkv, g_qkv);
    cudaGetSymbolAddress((void**)&px1,  g_x1);
    cudaGetSymbolAddress((void**)&pt,   g_t);
    cudaGetSymbolAddress((void**)&pah,  g_ah);
    cudaGetSymbolAddress((void**)&pal,  g_al);
    cudaGetSymbolAddress((void**)&puh,  g_uh);
    cudaGetSymbolAddress((void**)&pul,  g_ul);
    cudaGetSymbolAddress((void**)&pwqh, g_wqkv_h);
    cudaGetSymbolAddress((void**)&pwql, g_wqkv_l);
    cudaGetSymbolAddress((void**)&pwph, g_wp_h);
    cudaGetSymbolAddress((void**)&pwpl, g_wp_l);
    cudaGetSymbolAddress((void**)&pw1h, g_w1_h);
    cudaGetSymbolAddress((void**)&pw1l, g_w1_l);
    cudaGetSymbolAddress((void**)&pw2h, g_w2_h);
    cudaGetSymbolAddress((void**)&pw2l, g_w2_l);

    cudaFuncSetAttribute(gemm_mma_kernel<false, false, false, false>,
                         cudaFuncAttributeMaxDynamicSharedMemorySize, G_SMEM);
    cudaFuncSetAttribute(gemm_mma_kernel<true, false, true, false>,
                         cudaFuncAttributeMaxDynamicSharedMemorySize, G_SMEM);
    cudaFuncSetAttribute(gemm_mma_kernel<true, true, false, true>,
                         cudaFuncAttributeMaxDynamicSharedMemorySize, G_SMEM);
    int attn_smem = (64 * QLD + 64 * KLD + 128 * VLD + 128 * PLD) * (int)sizeof(float);
    cudaFuncSetAttribute(attn_kernel, cudaFuncAttributeMaxDynamicSharedMemorySize, attn_smem);

    dim3 tb(32, 8);
    // --- weight prep ---
    pack_qkv_tiled<<<dim3(EMB / 32, HEAD_SZ / 32, 48), tb>>>(wq, wk, wv);
    tsplit_w_tiled<<<dim3(EMB / 32, EMB / 32), tb>>>(w_proj, pwph, pwpl, EMB, EMB);
    tsplit_w_tiled<<<dim3(FFD / 32, EMB / 32), tb>>>(w1, pw1h, pw1l, EMB, FFD);
    tsplit_w_tiled<<<dim3(EMB / 32, FFD / 32), tb>>>(w2, pw2h, pw2l, FFD, EMB);

    // --- LN1 fused split ---
    ln_split_kernel<<<BT, 256>>>(x, g1, be1, pah, pal);
    // --- qkv = h @ Wqkv ---
    gemm_mma_kernel<false, false, false, false><<<dim3(N_QKV / 128, BT / 128), 256, G_SMEM>>>(
        pah, pal, pwqh, pwql, nullptr, nullptr, pqkv, nullptr, nullptr, BT, N_QKV, EMB);
    // --- attention (writes split o to ah/al) ---
    attn_kernel<<<dim3(8, HEADS, 4), 256, attn_smem>>>();
    // --- x1 = x + o @ Wproj + b_proj ---
    gemm_mma_kernel<true, false, true, false><<<dim3(EMB / 128, BT / 128), 256, G_SMEM>>>(
        pah, pal, pwph, pwpl, b_proj, x, px1, nullptr, nullptr, BT, EMB, EMB);
    // --- t = LN(x1); split(LN(t)) ---
    ln_kernel<<<BT, 256>>>(px1, g2, be2, pt);
    ln_split_kernel<<<BT, 256>>>(pt, g2, be2, pah, pal);
    // --- u = relu(t2 @ W1 + b1) -> split bf16 ---
    gemm_mma_kernel<true, true, false, true><<<dim3(FFD / 128, BT / 128), 256, G_SMEM>>>(
        pah, pal, pw1h, pw1l, b1, nullptr, nullptr, puh, pul, BT, FFD, EMB);
    // --- out = x1 + u @ W2 + b2 ---
    gemm_mma_kernel<true, false, true, false><<<dim3(EMB / 128, BT / 128), 256, G_SMEM>>>(
        puh, pul, pw2h, pw2l, b2, px1, out, nullptr, nullptr, BT, EMB, FFD);
}

// round 7
// speedup vs baseline: 3.3592x; 1.4432x over previous
#include <cuda_runtime.h>
#include <cuda_bf16.h>
#include <cuda_fp16.h>
#include <math.h>
#include <stdint.h>

#define EMB 1024
#define HEADS 16
#define HEAD_SZ 64
#define BT 4096
#define FFD 4096
#define N_QKV 3072
#define QSCALE 0.18033688011112042f   // log2(e)/8

// ---------------- scratch (static device arrays; no allocation) ----------------
__device__ __half  g_qkv16[BT * N_QKV];         // 24 MB f16 qkv (q pre-scaled)
__device__ float g_x1  [BT * EMB];
__device__ float g_t   [BT * EMB];
__device__ __nv_bfloat16 g_ah[BT * EMB];        // activation hi
__device__ __nv_bfloat16 g_al[BT * EMB];        // activation lo
__device__ __nv_bfloat16 g_uh[BT * FFD];
__device__ __nv_bfloat16 g_ul[BT * FFD];
__device__ __nv_bfloat16 g_wqkv_h[N_QKV * EMB];
__device__ __nv_bfloat16 g_wqkv_l[N_QKV * EMB];
__device__ __nv_bfloat16 g_wp_h  [EMB * EMB];
__device__ __nv_bfloat16 g_wp_l  [EMB * EMB];
__device__ __nv_bfloat16 g_w1_h  [FFD * EMB];
__device__ __nv_bfloat16 g_w1_l  [FFD * EMB];
__device__ __nv_bfloat16 g_w2_h  [EMB * FFD];
__device__ __nv_bfloat16 g_w2_l  [EMB * FFD];

// ================= helpers =================
__device__ __forceinline__ uint32_t smem_u32(const void* p) {
    uint32_t a;
    asm("{ .reg .u64 t; cvta.to.shared.u64 t, %1; cvt.u32.u64 %0, t; }" : "=r"(a) : "l"(p));
    return a;
}
__device__ __forceinline__ void ldsm4(uint32_t& a, uint32_t& b, uint32_t& c, uint32_t& d,
                                      uint32_t addr) {
    asm volatile("ldmatrix.sync.aligned.m8n8.x4.shared.b16 {%0,%1,%2,%3}, [%4];"
                 : "=r"(a), "=r"(b), "=r"(c), "=r"(d) : "r"(addr));
}
__device__ __forceinline__ void ldsm4t(uint32_t& a, uint32_t& b, uint32_t& c, uint32_t& d,
                                       uint32_t addr) {
    asm volatile("ldmatrix.sync.aligned.m8n8.x4.trans.shared.b16 {%0,%1,%2,%3}, [%4];"
                 : "=r"(a), "=r"(b), "=r"(c), "=r"(d) : "r"(addr));
}
__device__ __forceinline__ void mma_bf16(float* c, const uint32_t* a, const uint32_t* b) {
    asm volatile("mma.sync.aligned.m16n8k16.row.col.f32.bf16.bf16.f32 "
                 "{%0,%1,%2,%3}, {%4,%5,%6,%7}, {%8,%9}, {%0,%1,%2,%3};"
                 : "+f"(c[0]), "+f"(c[1]), "+f"(c[2]), "+f"(c[3])
                 : "r"(a[0]), "r"(a[1]), "r"(a[2]), "r"(a[3]), "r"(b[0]), "r"(b[1]));
}
__device__ __forceinline__ void mma_f16(float* c, const uint32_t* a, const uint32_t* b) {
    asm volatile("mma.sync.aligned.m16n8k16.row.col.f32.f16.f16.f32 "
                 "{%0,%1,%2,%3}, {%4,%5,%6,%7}, {%8,%9}, {%0,%1,%2,%3};"
                 : "+f"(c[0]), "+f"(c[1]), "+f"(c[2]), "+f"(c[3])
                 : "r"(a[0]), "r"(a[1]), "r"(a[2]), "r"(a[3]), "r"(b[0]), "r"(b[1]));
}
__device__ __forceinline__ void cp_async16(uint32_t dst, const void* src) {
    asm volatile("cp.async.cg.shared.global [%0], [%1], 16;" :: "r"(dst), "l"(src));
}
#define CP_COMMIT() asm volatile("cp.async.commit_group;" ::: "memory")

__device__ __forceinline__ float ex2f(float x) {
    float r;
    asm("ex2.approx.f32 %0, %1;" : "=f"(r) : "f"(x));
    return r;
}
__device__ __forceinline__ void split1(float v, __nv_bfloat16& h, __nv_bfloat16& l) {
    h = __float2bfloat16(v);
    l = __float2bfloat16(v - __bfloat162float(h));
}
__device__ __forceinline__ uint32_t pack_h2(float a, float b) {
    __half2 h = __floats2half2_rn(a, b);
    return *(uint32_t*)&h;
}

// ================= weight prep kernels =================
__global__ void tsplit_w_tiled(const float* __restrict__ W,
                               __nv_bfloat16* __restrict__ oh,
                               __nv_bfloat16* __restrict__ ol, int K, int N) {
    __shared__ float tile[32][33];
    int nb = blockIdx.x * 32, kb = blockIdx.y * 32;
    int tx = threadIdx.x, ty = threadIdx.y;
    #pragma unroll
    for (int i = 0; i < 4; i++)
        tile[ty + i * 8][tx] = W[(size_t)(kb + ty + i * 8) * N + nb + tx];
    __syncthreads();
    #pragma unroll
    for (int i = 0; i < 4; i++) {
        float v = tile[tx][ty + i * 8];
        __nv_bfloat16 hh, ll; split1(v, hh, ll);
        size_t o = (size_t)(nb + ty + i * 8) * K + kb + tx;
        oh[o] = hh; ol[o] = ll;
    }
}

__global__ void pack_qkv_tiled(const float* __restrict__ wq,
                               const float* __restrict__ wk,
                               const float* __restrict__ wv) {
    __shared__ float tile[32][33];
    int hz = blockIdx.z;
    int sel = hz >> 4, h = hz & 15;
    const float* w = (sel == 0) ? wq : (sel == 1) ? wk : wv;
    int c0 = blockIdx.x * 32, d0 = blockIdx.y * 32;
    int tx = threadIdx.x, ty = threadIdx.y;
    const float* base = w + (size_t)h * EMB * HEAD_SZ;
    #pragma unroll
    for (int i = 0; i < 4; i++)
        tile[ty + i * 8][tx] = base[(size_t)(c0 + ty + i * 8) * HEAD_SZ + d0 + tx];
    __syncthreads();
    #pragma unroll
    for (int i = 0; i < 4; i++) {
        float v = tile[tx][ty + i * 8];
        __nv_bfloat16 hh, ll; split1(v, hh, ll);
        size_t n = (size_t)sel * 1024 + h * 64 + d0 + ty + i * 8;
        g_wqkv_h[n * EMB + c0 + tx] = hh;
        g_wqkv_l[n * EMB + c0 + tx] = ll;
    }
}

// ================= LayerNorm variants =================
__device__ __forceinline__ void ln_stats(float4 xv, int tid, float& mu, float& rstd) {
    float s  = xv.x + xv.y + xv.z + xv.w;
    float ss = xv.x*xv.x + xv.y*xv.y + xv.z*xv.z + xv.w*xv.w;
    #pragma unroll
    for (int o = 16; o; o >>= 1) {
        s  += __shfl_xor_sync(0xffffffffu, s,  o);
        ss += __shfl_xor_sync(0xffffffffu, ss, o);
    }
    __shared__ float rs[8], rss[8];
    int wid = tid >> 5, lane = tid & 31;
    if (!lane) { rs[wid] = s; rss[wid] = ss; }
    __syncthreads();
    s = 0.f; ss = 0.f;
    #pragma unroll
    for (int i = 0; i < 8; i++) { s += rs[i]; ss += rss[i]; }
    mu = s * (1.0f / EMB);
    float var = ss * (1.0f / EMB) - mu * mu;
    rstd = rsqrtf(var + 1e-5f);
}

__global__ __launch_bounds__(256) void ln_kernel(const float* __restrict__ in,
                                                 const float* __restrict__ gw,
                                                 const float* __restrict__ bw,
                                                 float* __restrict__ out) {
    int row = blockIdx.x;
    int tid = threadIdx.x;
    float4 xv = ((const float4*)(in + (size_t)row * EMB))[tid];
    float mu, rstd;
    ln_stats(xv, tid, mu, rstd);
    float4 gv = ((const float4*)gw)[tid];
    float4 bv = ((const float4*)bw)[tid];
    float4 ov;
    ov.x = (xv.x - mu) * rstd * gv.x + bv.x;
    ov.y = (xv.y - mu) * rstd * gv.y + bv.y;
    ov.z = (xv.z - mu) * rstd * gv.z + bv.z;
    ov.w = (xv.w - mu) * rstd * gv.w + bv.w;
    ((float4*)(out + (size_t)row * EMB))[tid] = ov;
}

__global__ __launch_bounds__(256) void ln_split_kernel(const float* __restrict__ in,
                                                       const float* __restrict__ gw,
                                                       const float* __restrict__ bw,
                                                       __nv_bfloat16* __restrict__ oh,
                                                       __nv_bfloat16* __restrict__ ol) {
    int row = blockIdx.x;
    int tid = threadIdx.x;
    float4 xv = ((const float4*)(in + (size_t)row * EMB))[tid];
    float mu, rstd;
    ln_stats(xv, tid, mu, rstd);
    float4 gv = ((const float4*)gw)[tid];
    float4 bv = ((const float4*)bw)[tid];
    float o[4];
    o[0] = (xv.x - mu) * rstd * gv.x + bv.x;
    o[1] = (xv.y - mu) * rstd * gv.y + bv.y;
    o[2] = (xv.z - mu) * rstd * gv.z + bv.z;
    o[3] = (xv.w - mu) * rstd * gv.w + bv.w;
    __nv_bfloat16 h[4], l[4];
    #pragma unroll
    for (int j = 0; j < 4; j++) split1(o[j], h[j], l[j]);
    *(uint2*)(oh + (size_t)row * EMB + tid * 4) = *(const uint2*)h;
    *(uint2*)(ol + (size_t)row * EMB + tid * 4) = *(const uint2*)l;
}

// ================= mma.sync GEMM (bf16x3 fp32 emulation) =================
// OMODE: 0 = fp32 C, 1 = split bf16 hi/lo, 2 = f16 qkv (q cols pre-scaled)
#define GT 16384
#define GSTAGE (4 * GT)
#define G_SMEM (2 * GSTAGE)

template<bool BIAS, bool RELU, bool RES, int OMODE>
__global__ __launch_bounds__(256, 1) void gemm_mma_kernel(
    const __nv_bfloat16* __restrict__ Ah, const __nv_bfloat16* __restrict__ Al,
    const __nv_bfloat16* __restrict__ Bh, const __nv_bfloat16* __restrict__ Bl,
    const float* __restrict__ bias, const float* __restrict__ res,
    float* __restrict__ C,
    __nv_bfloat16* __restrict__ Oh, __nv_bfloat16* __restrict__ Ol,
    __half* __restrict__ O16,
    int M, int N, int K)
{
    extern __shared__ __align__(1024) char smem[];
    int tid = threadIdx.x, lane = tid & 31, wid = tid >> 5;
    int m0 = blockIdx.y * 128, n0 = blockIdx.x * 128;
    int wm = (wid >> 2) * 64, wn = (wid & 3) * 32;

    const __nv_bfloat16* srcs[4] = {Ah + (size_t)m0 * K, Al + (size_t)m0 * K,
                                    Bh + (size_t)n0 * K, Bl + (size_t)n0 * K};
    int fr[4], fc[4];
    #pragma unroll
    for (int i = 0; i < 4; i++) {
        int flat = i * 256 + tid;
        fr[i] = flat >> 3;
        fc[i] = flat & 7;
    }

    int nst = K >> 6;

    {   // prologue: stage 0
        char* buf = smem;
        #pragma unroll
        for (int t = 0; t < 4; t++)
            #pragma unroll
            for (int i = 0; i < 4; i++) {
                uint32_t sw = fr[i] * 128 + ((fc[i] ^ (fr[i] & 7)) * 16);
                cp_async16(smem_u32(buf + t * GT + sw),
                           srcs[t] + (size_t)fr[i] * K + fc[i] * 8);
            }
        CP_COMMIT();
    }

    float acc[4][4][4];
    #pragma unroll
    for (int i = 0; i < 4; i++)
        #pragma unroll
        for (int j = 0; j < 4; j++)
            #pragma unroll
            for (int r = 0; r < 4; r++) acc[i][j][r] = 0.f;

    for (int kt = 0; kt < nst; kt++) {
        if (kt + 1 < nst) {
            char* buf = smem + ((kt + 1) & 1) * GSTAGE;
            int ko = (kt + 1) * 64;
            #pragma unroll
            for (int t = 0; t < 4; t++)
                #pragma unroll
                for (int i = 0; i < 4; i++) {
                    uint32_t sw = fr[i] * 128 + ((fc[i] ^ (fr[i] & 7)) * 16);
                    cp_async16(smem_u32(buf + t * GT + sw),
                               srcs[t] + (size_t)fr[i] * K + ko + fc[i] * 8);
                }
            CP_COMMIT();
            asm volatile("cp.async.wait_group 1;" ::: "memory");
        } else {
            asm volatile("cp.async.wait_group 0;" ::: "memory");
        }
        __syncthreads();

        char* buf = smem + (kt & 1) * GSTAGE;
        uint32_t aH = smem_u32(buf);
        uint32_t aL = aH + GT, bH = aH + 2 * GT, bL = aH + 3 * GT;

        #pragma unroll
        for (int kk = 0; kk < 4; kk++) {
            uint32_t ah[4][4], al[4][4];
            #pragma unroll
            for (int i = 0; i < 4; i++) {
                int arow = wm + i * 16 + (lane & 15);
                uint32_t off = arow * 128 + (((kk * 2 + (lane >> 4)) ^ (arow & 7)) * 16);
                ldsm4(ah[i][0], ah[i][1], ah[i][2], ah[i][3], aH + off);
                ldsm4(al[i][0], al[i][1], al[i][2], al[i][3], aL + off);
            }
            uint32_t bh[4][2], bl[4][2];
            #pragma unroll
            for (int jp = 0; jp < 2; jp++) {
                int brow = wn + (jp * 2 + (lane >> 4)) * 8 + (lane & 7);
                int sub = (lane >> 3) & 1;
                uint32_t off = brow * 128 + (((kk * 2 + sub) ^ (brow & 7)) * 16);
                uint32_t r0, r1, r2, r3;
                ldsm4(r0, r1, r2, r3, bH + off);
                bh[jp * 2][0] = r0; bh[jp * 2][1] = r1;
                bh[jp * 2 + 1][0] = r2; bh[jp * 2 + 1][1] = r3;
                ldsm4(r0, r1, r2, r3, bL + off);
                bl[jp * 2][0] = r0; bl[jp * 2][1] = r1;
                bl[jp * 2 + 1][0] = r2; bl[jp * 2 + 1][1] = r3;
            }
            #pragma unroll
            for (int i = 0; i < 4; i++)
                #pragma unroll
                for (int j = 0; j < 4; j++) {
                    mma_bf16(acc[i][j], ah[i], bh[j]);
                    mma_bf16(acc[i][j], ah[i], bl[j]);
                    mma_bf16(acc[i][j], al[i], bh[j]);
                }
        }
        __syncthreads();
    }

    // epilogue
    float qsc = 1.0f;
    if (OMODE == 2) qsc = (n0 < 1024) ? QSCALE : 1.0f;
    int r_lo = lane >> 2, c_lo = (lane & 3) * 2;
    #pragma unroll
    for (int i = 0; i < 4; i++)
        #pragma unroll
        for (int rr = 0; rr < 2; rr++) {
            int m = m0 + wm + i * 16 + r_lo + rr * 8;
            const float* rrow = RES ? (res + (size_t)m * N) : (const float*)0;
            #pragma unroll
            for (int j = 0; j < 4; j++) {
                int n = n0 + wn + j * 8 + c_lo;
                float2 v = make_float2(acc[i][j][rr * 2], acc[i][j][rr * 2 + 1]);
                if (BIAS) {
                    float2 b2v = *(const float2*)(bias + n);
                    v.x += b2v.x; v.y += b2v.y;
                }
                if (RELU) { v.x = fmaxf(v.x, 0.f); v.y = fmaxf(v.y, 0.f); }
                if (RES) {
                    float2 r2v = *(const float2*)(rrow + n);
                    v.x += r2v.x; v.y += r2v.y;
                }
                if (OMODE == 1) {
                    __nv_bfloat16 hx, lx, hy, ly;
                    split1(v.x, hx, lx);
                    split1(v.y, hy, ly);
                    __nv_bfloat162 hp, lp;
                    hp.x = hx; hp.y = hy;
                    lp.x = lx; lp.y = ly;
                    *(__nv_bfloat162*)(Oh + (size_t)m * N + n) = hp;
                    *(__nv_bfloat162*)(Ol + (size_t)m * N + n) = lp;
                } else if (OMODE == 2) {
                    __half2 hp = __floats2half2_rn(v.x * qsc, v.y * qsc);
                    *(__half2*)(O16 + (size_t)m * N + n) = hp;
                } else {
                    *(float2*)(C + (size_t)m * N + n) = v;
                }
            }
        }
}

// ================= f16 mma flash attention =================
// grid (8 q-tiles, 16 heads, 4 batch), 256 threads (8 warps), warp = 16 q rows.
// smem: Q 16K | K0 16K | V0 16K | K1 16K | V1 16K = 80 KB
#define ATT_SMEM (80 * 1024)

__global__ __launch_bounds__(256) void attn_mma_kernel(const __half* __restrict__ qkv) {
    extern __shared__ __align__(1024) char smem[];
    int tid = threadIdx.x, lane = tid & 31, w = tid >> 5;
    int tile = blockIdx.x, h = blockIdx.y, b = blockIdx.z;
    int t0 = tile * 128;

    const __half* qb = qkv + (size_t)(b * 1024 + t0) * N_QKV + h * HEAD_SZ;
    const __half* kb = qkv + (size_t)(b * 1024) * N_QKV + 1024 + h * HEAD_SZ;
    const __half* vb = qkv + (size_t)(b * 1024) * N_QKV + 2048 + h * HEAD_SZ;

    int fr[4], fc[4];
    #pragma unroll
    for (int i = 0; i < 4; i++) {
        int flat = i * 256 + tid;
        fr[i] = flat >> 3;
        fc[i] = flat & 7;
    }

    // prologue: Q + K0 + V0 (group 0)
    #pragma unroll
    for (int i = 0; i < 4; i++) {
        uint32_t sw = fr[i] * 128 + ((fc[i] ^ (fr[i] & 7)) * 16);
        size_t go = (size_t)fr[i] * N_QKV + fc[i] * 8;
        cp_async16(smem_u32(smem + sw), qb + go);
        cp_async16(smem_u32(smem + 16384 + sw), kb + go);
        cp_async16(smem_u32(smem + 32768 + sw), vb + go);
    }
    CP_COMMIT();

    uint32_t qa[4][4];
    float m1 = -INFINITY, m2 = -INFINITY, l1 = 0.f, l2 = 0.f;
    float oacc[8][4];
    #pragma unroll
    for (int j = 0; j < 8; j++)
        #pragma unroll
        for (int r = 0; r < 4; r++) oacc[j][r] = 0.f;

    for (int kt = 0; kt < 8; kt++) {
        if (kt) __syncthreads();          // protect smem buffer reuse
        if (kt + 1 < 8) {
            const __half* ks = kb + (size_t)(kt + 1) * 128 * N_QKV;
            const __half* vs = vb + (size_t)(kt + 1) * 128 * N_QKV;
            char* kd = smem + 16384 + ((kt + 1) & 1) * 32768;
            #pragma unroll
            for (int i = 0; i < 4; i++) {
                uint32_t sw = fr[i] * 128 + ((fc[i] ^ (fr[i] & 7)) * 16);
                size_t go = (size_t)fr[i] * N_QKV + fc[i] * 8;
                cp_async16(smem_u32(kd + sw), ks + go);
                cp_async16(smem_u32(kd + 16384 + sw), vs + go);
            }
            CP_COMMIT();
            asm volatile("cp.async.wait_group 1;" ::: "memory");
        } else {
            asm volatile("cp.async.wait_group 0;" ::: "memory");
        }
        __syncthreads();

        if (kt == 0) {
            uint32_t qbase = smem_u32(smem);
            #pragma unroll
            for (int kk = 0; kk < 4; kk++) {
                int arow = w * 16 + (lane & 15);
                uint32_t off = arow * 128 + (((kk * 2 + (lane >> 4)) ^ (arow & 7)) * 16);
                ldsm4(qa[kk][0], qa[kk][1], qa[kk][2], qa[kk][3], qbase + off);
            }
        }

        uint32_t kbase = smem_u32(smem + 16384 + (kt & 1) * 32768);
        uint32_t vbase = kbase + 16384;

        // ---- S = Q K^T (f16, fp32 acc, log2-scaled) ----
        float sacc[16][4];
        #pragma unroll
        for (int j = 0; j < 16; j++)
            #pragma unroll
            for (int r = 0; r < 4; r++) sacc[j][r] = 0.f;

        #pragma unroll
        for (int kk = 0; kk < 4; kk++) {
            #pragma unroll
            for (int jp = 0; jp < 8; jp++) {
                int brow = (jp * 2 + (lane >> 4)) * 8 + (lane & 7);
                int sub = (lane >> 3) & 1;
                uint32_t off = brow * 128 + (((kk * 2 + sub) ^ (brow & 7)) * 16);
                uint32_t bb[4];
                ldsm4(bb[0], bb[1], bb[2], bb[3], kbase + off);
                mma_f16(sacc[jp * 2], qa[kk], bb);
                mma_f16(sacc[jp * 2 + 1], qa[kk], bb + 2);
            }
        }

        // ---- online softmax (base 2) ----
        float mt1 = -INFINITY, mt2 = -INFINITY;
        #pragma unroll
        for (int j = 0; j < 16; j++) {
            mt1 = fmaxf(mt1, fmaxf(sacc[j][0], sacc[j][1]));
            mt2 = fmaxf(mt2, fmaxf(sacc[j][2], sacc[j][3]));
        }
        mt1 = fmaxf(mt1, __shfl_xor_sync(0xffffffffu, mt1, 1));
        mt1 = fmaxf(mt1, __shfl_xor_sync(0xffffffffu, mt1, 2));
        mt2 = fmaxf(mt2, __shfl_xor_sync(0xffffffffu, mt2, 1));
        mt2 = fmaxf(mt2, __shfl_xor_sync(0xffffffffu, mt2, 2));
        float mn1 = fmaxf(m1, mt1), mn2 = fmaxf(m2, mt2);
        float al1 = ex2f(m1 - mn1), al2 = ex2f(m2 - mn2);
        m1 = mn1; m2 = mn2;

        uint32_t ph[16], ph2[16];
        float ls1 = 0.f, ls2 = 0.f;
        #pragma unroll
        for (int j = 0; j < 16; j++) {
            float p0 = ex2f(sacc[j][0] - mn1);
            float p1 = ex2f(sacc[j][1] - mn1);
            float p2 = ex2f(sacc[j][2] - mn2);
            float p3 = ex2f(sacc[j][3] - mn2);
            ls1 += p0 + p1;
            ls2 += p2 + p3;
            ph[j]  = pack_h2(p0, p1);
            ph2[j] = pack_h2(p2, p3);
        }
        l1 = l1 * al1 + ls1;
        l2 = l2 * al2 + ls2;
        #pragma unroll
        for (int j = 0; j < 8; j++) {
            oacc[j][0] *= al1; oacc[j][1] *= al1;
            oacc[j][2] *= al2; oacc[j][3] *= al2;
        }

        // ---- O += P V (f16) ----
        #pragma unroll
        for (int kk2 = 0; kk2 < 8; kk2++) {
            uint32_t pa[4] = {ph[kk2 * 2], ph2[kk2 * 2], ph[kk2 * 2 + 1], ph2[kk2 * 2 + 1]};
            #pragma unroll
            for (int jp2 = 0; jp2 < 4; jp2++) {
                int srow = kk2 * 16 + ((lane >> 3) & 1) * 8 + (lane & 7);
                int ch = jp2 * 2 + (lane >> 4);
                uint32_t off = srow * 128 + ((ch ^ (srow & 7)) * 16);
                uint32_t bb[4];
                ldsm4t(bb[0], bb[1], bb[2], bb[3], vbase + off);
                mma_f16(oacc[jp2 * 2], pa, bb);
                mma_f16(oacc[jp2 * 2 + 1], pa, bb + 2);
            }
        }
    }

    // ---- epilogue: o = oacc / l, split to bf16 hi/lo ----
    l1 += __shfl_xor_sync(0xffffffffu, l1, 1);
    l1 += __shfl_xor_sync(0xffffffffu, l1, 2);
    l2 += __shfl_xor_sync(0xffffffffu, l2, 1);
    l2 += __shfl_xor_sync(0xffffffffu, l2, 2);
    float inv1 = 1.0f / l1, inv2 = 1.0f / l2;

    int r1 = t0 + w * 16 + (lane >> 2);
    int r2 = r1 + 8;
    size_t row1 = (size_t)(b * 1024 + r1) * EMB + h * HEAD_SZ;
    size_t row2 = (size_t)(b * 1024 + r2) * EMB + h * HEAD_SZ;
    #pragma unroll
    for (int j = 0; j < 8; j++) {
        int d = j * 8 + (lane & 3) * 2;
        float o0 = oacc[j][0] * inv1, o1 = oacc[j][1] * inv1;
        float o2 = oacc[j][2] * inv2, o3 = oacc[j][3] * inv2;
        __nv_bfloat16 h0, l0, h1, lo1, h2b, l2b, h3, l3;
        split1(o0, h0, l0); split1(o1, h1, lo1);
        split1(o2, h2b, l2b); split1(o3, h3, l3);
        __nv_bfloat162 hp1; hp1.x = h0; hp1.y = h1;
        __nv_bfloat162 lp1; lp1.x = l0; lp1.y = lo1;
        __nv_bfloat162 hp2; hp2.x = h2b; hp2.y = h3;
        __nv_bfloat162 lp2; lp2.x = l2b; lp2.y = l3;
        *(__nv_bfloat162*)(g_ah + row1 + d) = hp1;
        *(__nv_bfloat162*)(g_al + row1 + d) = lp1;
        *(__nv_bfloat162*)(g_ah + row2 + d) = hp2;
        *(__nv_bfloat162*)(g_al + row2 + d) = lp2;
    }
}

// ================= launch =================
extern "C" void kernel_launch(void* const* d_in, const int* in_sizes, int n_in,
                              void* d_out, int out_size) {
    const float* x      = (const float*)d_in[0];
    const float* wq     = (const float*)d_in[1];
    const float* wk     = (const float*)d_in[2];
    const float* wv     = (const float*)d_in[3];
    const float* w_proj = (const float*)d_in[4];
    const float* b_proj = (const float*)d_in[5];
    const float* w1     = (const float*)d_in[6];
    const float* b1     = (const float*)d_in[7];
    const float* w2     = (const float*)d_in[8];
    const float* b2     = (const float*)d_in[9];
    const float* g1     = (const float*)d_in[10];
    const float* be1    = (const float*)d_in[11];
    const float* g2     = (const float*)d_in[12];
    const float* be2    = (const float*)d_in[13];
    float* out = (float*)d_out;

    float *px1, *pt;
    __half* pq16;
    __nv_bfloat16 *pah, *pal, *puh, *pul, *pwqh, *pwql, *pwph, *pwpl, *pw1h, *pw1l, *pw2h, *pw2l;
    cudaGetSymbolAddress((void**)&pq16, g_qkv16);
    cudaGetSymbolAddress((void**)&px1,  g_x1);
    cudaGetSymbolAddress((void**)&pt,   g_t);
    cudaGetSymbolAddress((void**)&pah,  g_ah);
    cudaGetSymbolAddress((void**)&pal,  g_al);
    cudaGetSymbolAddress((void**)&puh,  g_uh);
    cudaGetSymbolAddress((void**)&pul,  g_ul);
    cudaGetSymbolAddress((void**)&pwqh, g_wqkv_h);
    cudaGetSymbolAddress((void**)&pwql, g_wqkv_l);
    cudaGetSymbolAddress((void**)&pwph, g_wp_h);
    cudaGetSymbolAddress((void**)&pwpl, g_wp_l);
    cudaGetSymbolAddress((void**)&pw1h, g_w1_h);
    cudaGetSymbolAddress((void**)&pw1l, g_w1_l);
    cudaGetSymbolAddress((void**)&pw2h, g_w2_h);
    cudaGetSymbolAddress((void**)&pw2l, g_w2_l);

    cudaFuncSetAttribute(gemm_mma_kernel<false, false, false, 2>,
                         cudaFuncAttributeMaxDynamicSharedMemorySize, G_SMEM);
    cudaFuncSetAttribute(gemm_mma_kernel<true, false, true, 0>,
                         cudaFuncAttributeMaxDynamicSharedMemorySize, G_SMEM);
    cudaFuncSetAttribute(gemm_mma_kernel<true, true, false, 1>,
                         cudaFuncAttributeMaxDynamicSharedMemorySize, G_SMEM);
    cudaFuncSetAttribute(attn_mma_kernel,
                         cudaFuncAttributeMaxDynamicSharedMemorySize, ATT_SMEM);

    dim3 tb(32, 8);
    // --- weight prep ---
    pack_qkv_tiled<<<dim3(EMB / 32, HEAD_SZ / 32, 48), tb>>>(wq, wk, wv);
    tsplit_w_tiled<<<dim3(EMB / 32, EMB / 32), tb>>>(w_proj, pwph, pwpl, EMB, EMB);
    tsplit_w_tiled<<<dim3(FFD / 32, EMB / 32), tb>>>(w1, pw1h, pw1l, EMB, FFD);
    tsplit_w_tiled<<<dim3(EMB / 32, FFD / 32), tb>>>(w2, pw2h, pw2l, FFD, EMB);

    // --- LN1 fused split ---
    ln_split_kernel<<<BT, 256>>>(x, g1, be1, pah, pal);
    // --- qkv (f16 out, q pre-scaled by log2e/8) ---
    gemm_mma_kernel<false, false, false, 2><<<dim3(N_QKV / 128, BT / 128), 256, G_SMEM>>>(
        pah, pal, pwqh, pwql, nullptr, nullptr, nullptr, nullptr, nullptr, pq16,
        BT, N_QKV, EMB);
    // --- attention (f16 mma flash; writes split bf16 o to ah/al) ---
    attn_mma_kernel<<<dim3(8, HEADS, 4), 256, ATT_SMEM>>>(pq16);
    // --- x1 = x + o @ Wproj + b_proj ---
    gemm_mma_kernel<true, false, true, 0><<<dim3(EMB / 128, BT / 128), 256, G_SMEM>>>(
        pah, pal, pwph, pwpl, b_proj, x, px1, nullptr, nullptr, nullptr, BT, EMB, EMB);
    // --- t = LN(x1); split(LN(t)) ---
    ln_kernel<<<BT, 256>>>(px1, g2, be2, pt);
    ln_split_kernel<<<BT, 256>>>(pt, g2, be2, pah, pal);
    // --- u = relu(t2 @ W1 + b1) -> split bf16 ---
    gemm_mma_kernel<true, true, false, 1><<<dim3(FFD / 128, BT / 128), 256, G_SMEM>>>(
        pah, pal, pw1h, pw1l, b1, nullptr, nullptr, puh, pul, nullptr, BT, FFD, EMB);
    // --- out = x1 + u @ W2 + b2 ---
    gemm_mma_kernel<true, false, true, 0><<<dim3(EMB / 128, BT / 128), 256, G_SMEM>>>(
        puh, pul, pw2h, pw2l, b2, px1, out, nullptr, nullptr, nullptr, BT, EMB, FFD);
}

// round 8
// speedup vs baseline: 6.6883x; 1.9911x over previous
#include <cuda_runtime.h>
#include <cuda_bf16.h>
#include <cuda_fp16.h>
#include <math.h>
#include <stdint.h>

#define EMB 1024
#define HEADS 16
#define HEAD_SZ 64
#define BT 4096
#define FFD 4096
#define N_QKV 3072
#define QSCALE 0.18033688011112042f   // log2(e)/8

// ---------------- scratch (static device arrays; no allocation) ----------------
__device__ __half g_qkv16[BT * N_QKV];    // f16 qkv (q pre-scaled)
__device__ __half g_a16  [BT * EMB];      // f16 activations (LN1 out / attn out / LN2 out)
__device__ __half g_u16  [BT * FFD];      // f16 FF hidden
__device__ float  g_x1   [BT * EMB];
__device__ float  g_t    [BT * EMB];
// f16 transposed weights, Bt[N][K] layout (K contiguous)
__device__ __half g_wqkv16[N_QKV * EMB];
__device__ __half g_wp16  [EMB * EMB];
__device__ __half g_w116  [FFD * EMB];
__device__ __half g_w216  [EMB * FFD];

// ================= helpers =================
__device__ __forceinline__ uint32_t smem_u32(const void* p) {
    uint32_t a;
    asm("{ .reg .u64 t; cvta.to.shared.u64 t, %1; cvt.u32.u64 %0, t; }" : "=r"(a) : "l"(p));
    return a;
}
__device__ __forceinline__ void ldsm4(uint32_t& a, uint32_t& b, uint32_t& c, uint32_t& d,
                                      uint32_t addr) {
    asm volatile("ldmatrix.sync.aligned.m8n8.x4.shared.b16 {%0,%1,%2,%3}, [%4];"
                 : "=r"(a), "=r"(b), "=r"(c), "=r"(d) : "r"(addr));
}
__device__ __forceinline__ void ldsm4t(uint32_t& a, uint32_t& b, uint32_t& c, uint32_t& d,
                                       uint32_t addr) {
    asm volatile("ldmatrix.sync.aligned.m8n8.x4.trans.shared.b16 {%0,%1,%2,%3}, [%4];"
                 : "=r"(a), "=r"(b), "=r"(c), "=r"(d) : "r"(addr));
}
__device__ __forceinline__ void mma_f16(float* c, const uint32_t* a, const uint32_t* b) {
    asm volatile("mma.sync.aligned.m16n8k16.row.col.f32.f16.f16.f32 "
                 "{%0,%1,%2,%3}, {%4,%5,%6,%7}, {%8,%9}, {%0,%1,%2,%3};"
                 : "+f"(c[0]), "+f"(c[1]), "+f"(c[2]), "+f"(c[3])
                 : "r"(a[0]), "r"(a[1]), "r"(a[2]), "r"(a[3]), "r"(b[0]), "r"(b[1]));
}
__device__ __forceinline__ void cp_async16(uint32_t dst, const void* src) {
    asm volatile("cp.async.cg.shared.global [%0], [%1], 16;" :: "r"(dst), "l"(src));
}
#define CP_COMMIT() asm volatile("cp.async.commit_group;" ::: "memory")

__device__ __forceinline__ float ex2f(float x) {
    float r;
    asm("ex2.approx.f32 %0, %1;" : "=f"(r) : "f"(x));
    return r;
}
__device__ __forceinline__ uint32_t pack_h2(float a, float b) {
    __half2 h = __floats2half2_rn(a, b);
    return *(uint32_t*)&h;
}

// ================= weight prep kernels =================
// tiled transpose+convert: W[K,N] -> Wt[N,K] f16. block (32,8), grid (N/32, K/32)
__global__ void tconv_w_tiled(const float* __restrict__ W,
                              __half* __restrict__ o16, int K, int N) {
    __shared__ float tile[32][33];
    int nb = blockIdx.x * 32, kb = blockIdx.y * 32;
    int tx = threadIdx.x, ty = threadIdx.y;
    #pragma unroll
    for (int i = 0; i < 4; i++)
        tile[ty + i * 8][tx] = W[(size_t)(kb + ty + i * 8) * N + nb + tx];
    __syncthreads();
    #pragma unroll
    for (int i = 0; i < 4; i++) {
        size_t o = (size_t)(nb + ty + i * 8) * K + kb + tx;
        o16[o] = __float2half(tile[tx][ty + i * 8]);
    }
}

// pack+transpose+convert qkv: w[h][c][d] -> Bt[n=sel*1024+h*64+d][k=c] f16
__global__ void pack_qkv_tiled(const float* __restrict__ wq,
                               const float* __restrict__ wk,
                               const float* __restrict__ wv) {
    __shared__ float tile[32][33];
    int hz = blockIdx.z;
    int sel = hz >> 4, h = hz & 15;
    const float* w = (sel == 0) ? wq : (sel == 1) ? wk : wv;
    int c0 = blockIdx.x * 32, d0 = blockIdx.y * 32;
    int tx = threadIdx.x, ty = threadIdx.y;
    const float* base = w + (size_t)h * EMB * HEAD_SZ;
    #pragma unroll
    for (int i = 0; i < 4; i++)
        tile[ty + i * 8][tx] = base[(size_t)(c0 + ty + i * 8) * HEAD_SZ + d0 + tx];
    __syncthreads();
    #pragma unroll
    for (int i = 0; i < 4; i++) {
        size_t n = (size_t)sel * 1024 + h * 64 + d0 + ty + i * 8;
        g_wqkv16[n * EMB + c0 + tx] = __float2half(tile[tx][ty + i * 8]);
    }
}

// ================= LayerNorm variants =================
__device__ __forceinline__ void ln_stats(float4 xv, int tid, float& mu, float& rstd) {
    float s  = xv.x + xv.y + xv.z + xv.w;
    float ss = xv.x*xv.x + xv.y*xv.y + xv.z*xv.z + xv.w*xv.w;
    #pragma unroll
    for (int o = 16; o; o >>= 1) {
        s  += __shfl_xor_sync(0xffffffffu, s,  o);
        ss += __shfl_xor_sync(0xffffffffu, ss, o);
    }
    __shared__ float rs[8], rss[8];
    int wid = tid >> 5, lane = tid & 31;
    if (!lane) { rs[wid] = s; rss[wid] = ss; }
    __syncthreads();
    s = 0.f; ss = 0.f;
    #pragma unroll
    for (int i = 0; i < 8; i++) { s += rs[i]; ss += rss[i]; }
    mu = s * (1.0f / EMB);
    float var = ss * (1.0f / EMB) - mu * mu;
    rstd = rsqrtf(var + 1e-5f);
}

__global__ __launch_bounds__(256) void ln_kernel(const float* __restrict__ in,
                                                 const float* __restrict__ gw,
                                                 const float* __restrict__ bw,
                                                 float* __restrict__ out) {
    int row = blockIdx.x;
    int tid = threadIdx.x;
    float4 xv = ((const float4*)(in + (size_t)row * EMB))[tid];
    float mu, rstd;
    ln_stats(xv, tid, mu, rstd);
    float4 gv = ((const float4*)gw)[tid];
    float4 bv = ((const float4*)bw)[tid];
    float4 ov;
    ov.x = (xv.x - mu) * rstd * gv.x + bv.x;
    ov.y = (xv.y - mu) * rstd * gv.y + bv.y;
    ov.z = (xv.z - mu) * rstd * gv.z + bv.z;
    ov.w = (xv.w - mu) * rstd * gv.w + bv.w;
    ((float4*)(out + (size_t)row * EMB))[tid] = ov;
}

__global__ __launch_bounds__(256) void ln_f16_kernel(const float* __restrict__ in,
                                                     const float* __restrict__ gw,
                                                     const float* __restrict__ bw,
                                                     __half* __restrict__ o16) {
    int row = blockIdx.x;
    int tid = threadIdx.x;
    float4 xv = ((const float4*)(in + (size_t)row * EMB))[tid];
    float mu, rstd;
    ln_stats(xv, tid, mu, rstd);
    float4 gv = ((const float4*)gw)[tid];
    float4 bv = ((const float4*)bw)[tid];
    __half2 p0 = __floats2half2_rn((xv.x - mu) * rstd * gv.x + bv.x,
                                   (xv.y - mu) * rstd * gv.y + bv.y);
    __half2 p1 = __floats2half2_rn((xv.z - mu) * rstd * gv.z + bv.z,
                                   (xv.w - mu) * rstd * gv.w + bv.w);
    uint2 pk; pk.x = *(uint32_t*)&p0; pk.y = *(uint32_t*)&p1;
    *(uint2*)(o16 + (size_t)row * EMB + tid * 4) = pk;
}

// ================= mma.sync GEMM (single-pass f16) =================
// C[M,N] = A[M,K] @ Bt[N,K]^T. CTA 128x128, BK=64, double-buffered cp.async.
// 8 warps: warp tile 64(m) x 32(n). 128B-row XOR swizzle in smem.
// OMODE: 0 = fp32 C, 1 = f16 out, 2 = f16 qkv out (q cols pre-scaled)
#define GT 16384
#define GSTAGE (2 * GT)
#define G_SMEM (2 * GSTAGE)     // 64 KB

template<bool BIAS, bool RELU, bool RES, int OMODE>
__global__ __launch_bounds__(256, 1) void gemm_mma_kernel(
    const __half* __restrict__ A, const __half* __restrict__ B,
    const float* __restrict__ bias, const float* __restrict__ res,
    float* __restrict__ C, __half* __restrict__ O16,
    int M, int N, int K)
{
    extern __shared__ __align__(1024) char smem[];
    int tid = threadIdx.x, lane = tid & 31, wid = tid >> 5;
    int m0 = blockIdx.y * 128, n0 = blockIdx.x * 128;
    int wm = (wid >> 2) * 64, wn = (wid & 3) * 32;

    const __half* srcs[2] = {A + (size_t)m0 * K, B + (size_t)n0 * K};
    int fr[4], fc[4];
    #pragma unroll
    for (int i = 0; i < 4; i++) {
        int flat = i * 256 + tid;
        fr[i] = flat >> 3;
        fc[i] = flat & 7;
    }

    int nst = K >> 6;

    {   // prologue: stage 0
        #pragma unroll
        for (int t = 0; t < 2; t++)
            #pragma unroll
            for (int i = 0; i < 4; i++) {
                uint32_t sw = fr[i] * 128 + ((fc[i] ^ (fr[i] & 7)) * 16);
                cp_async16(smem_u32(smem + t * GT + sw),
                           srcs[t] + (size_t)fr[i] * K + fc[i] * 8);
            }
        CP_COMMIT();
    }

    float acc[4][4][4];
    #pragma unroll
    for (int i = 0; i < 4; i++)
        #pragma unroll
        for (int j = 0; j < 4; j++)
            #pragma unroll
            for (int r = 0; r < 4; r++) acc[i][j][r] = 0.f;

    for (int kt = 0; kt < nst; kt++) {
        if (kt + 1 < nst) {
            char* buf = smem + ((kt + 1) & 1) * GSTAGE;
            int ko = (kt + 1) * 64;
            #pragma unroll
            for (int t = 0; t < 2; t++)
                #pragma unroll
                for (int i = 0; i < 4; i++) {
                    uint32_t sw = fr[i] * 128 + ((fc[i] ^ (fr[i] & 7)) * 16);
                    cp_async16(smem_u32(buf + t * GT + sw),
                               srcs[t] + (size_t)fr[i] * K + ko + fc[i] * 8);
                }
            CP_COMMIT();
            asm volatile("cp.async.wait_group 1;" ::: "memory");
        } else {
            asm volatile("cp.async.wait_group 0;" ::: "memory");
        }
        __syncthreads();

        char* buf = smem + (kt & 1) * GSTAGE;
        uint32_t aB = smem_u32(buf);
        uint32_t bB = aB + GT;

        #pragma unroll
        for (int kk = 0; kk < 4; kk++) {
            uint32_t ah[4][4];
            #pragma unroll
            for (int i = 0; i < 4; i++) {
                int arow = wm + i * 16 + (lane & 15);
                uint32_t off = arow * 128 + (((kk * 2 + (lane >> 4)) ^ (arow & 7)) * 16);
                ldsm4(ah[i][0], ah[i][1], ah[i][2], ah[i][3], aB + off);
            }
            uint32_t bh[4][2];
            #pragma unroll
            for (int jp = 0; jp < 2; jp++) {
                int brow = wn + (jp * 2 + (lane >> 4)) * 8 + (lane & 7);
                int sub = (lane >> 3) & 1;
                uint32_t off = brow * 128 + (((kk * 2 + sub) ^ (brow & 7)) * 16);
                uint32_t r0, r1, r2, r3;
                ldsm4(r0, r1, r2, r3, bB + off);
                bh[jp * 2][0] = r0; bh[jp * 2][1] = r1;
                bh[jp * 2 + 1][0] = r2; bh[jp * 2 + 1][1] = r3;
            }
            #pragma unroll
            for (int i = 0; i < 4; i++)
                #pragma unroll
                for (int j = 0; j < 4; j++)
                    mma_f16(acc[i][j], ah[i], bh[j]);
        }
        __syncthreads();
    }

    // epilogue
    float qsc = 1.0f;
    if (OMODE == 2) qsc = (n0 < 1024) ? QSCALE : 1.0f;
    int r_lo = lane >> 2, c_lo = (lane & 3) * 2;
    #pragma unroll
    for (int i = 0; i < 4; i++)
        #pragma unroll
        for (int rr = 0; rr < 2; rr++) {
            int m = m0 + wm + i * 16 + r_lo + rr * 8;
            const float* rrow = RES ? (res + (size_t)m * N) : (const float*)0;
            #pragma unroll
            for (int j = 0; j < 4; j++) {
                int n = n0 + wn + j * 8 + c_lo;
                float2 v = make_float2(acc[i][j][rr * 2], acc[i][j][rr * 2 + 1]);
                if (BIAS) {
                    float2 b2v = *(const float2*)(bias + n);
                    v.x += b2v.x; v.y += b2v.y;
                }
                if (RELU) { v.x = fmaxf(v.x, 0.f); v.y = fmaxf(v.y, 0.f); }
                if (RES) {
                    float2 r2v = *(const float2*)(rrow + n);
                    v.x += r2v.x; v.y += r2v.y;
                }
                if (OMODE == 0) {
                    *(float2*)(C + (size_t)m * N + n) = v;
                } else {
                    float s = (OMODE == 2) ? qsc : 1.0f;
                    __half2 hp = __floats2half2_rn(v.x * s, v.y * s);
                    *(__half2*)(O16 + (size_t)m * N + n) = hp;
                }
            }
        }
}

// ================= f16 mma flash attention =================
// grid (8 q-tiles, 16 heads, 4 batch), 256 threads (8 warps), warp = 16 q rows.
// smem: Q 16K | K0 16K | V0 16K | K1 16K | V1 16K = 80 KB
#define ATT_SMEM (80 * 1024)

__global__ __launch_bounds__(256) void attn_mma_kernel(const __half* __restrict__ qkv) {
    extern __shared__ __align__(1024) char smem[];
    int tid = threadIdx.x, lane = tid & 31, w = tid >> 5;
    int tile = blockIdx.x, h = blockIdx.y, b = blockIdx.z;
    int t0 = tile * 128;

    const __half* qb = qkv + (size_t)(b * 1024 + t0) * N_QKV + h * HEAD_SZ;
    const __half* kb = qkv + (size_t)(b * 1024) * N_QKV + 1024 + h * HEAD_SZ;
    const __half* vb = qkv + (size_t)(b * 1024) * N_QKV + 2048 + h * HEAD_SZ;

    int fr[4], fc[4];
    #pragma unroll
    for (int i = 0; i < 4; i++) {
        int flat = i * 256 + tid;
        fr[i] = flat >> 3;
        fc[i] = flat & 7;
    }

    // prologue: Q + K0 + V0
    #pragma unroll
    for (int i = 0; i < 4; i++) {
        uint32_t sw = fr[i] * 128 + ((fc[i] ^ (fr[i] & 7)) * 16);
        size_t go = (size_t)fr[i] * N_QKV + fc[i] * 8;
        cp_async16(smem_u32(smem + sw), qb + go);
        cp_async16(smem_u32(smem + 16384 + sw), kb + go);
        cp_async16(smem_u32(smem + 32768 + sw), vb + go);
    }
    CP_COMMIT();

    uint32_t qa[4][4];
    float m1 = -INFINITY, m2 = -INFINITY, l1 = 0.f, l2 = 0.f;
    float oacc[8][4];
    #pragma unroll
    for (int j = 0; j < 8; j++)
        #pragma unroll
        for (int r = 0; r < 4; r++) oacc[j][r] = 0.f;

    for (int kt = 0; kt < 8; kt++) {
        if (kt) __syncthreads();
        if (kt + 1 < 8) {
            const __half* ks = kb + (size_t)(kt + 1) * 128 * N_QKV;
            const __half* vs = vb + (size_t)(kt + 1) * 128 * N_QKV;
            char* kd = smem + 16384 + ((kt + 1) & 1) * 32768;
            #pragma unroll
            for (int i = 0; i < 4; i++) {
                uint32_t sw = fr[i] * 128 + ((fc[i] ^ (fr[i] & 7)) * 16);
                size_t go = (size_t)fr[i] * N_QKV + fc[i] * 8;
                cp_async16(smem_u32(kd + sw), ks + go);
                cp_async16(smem_u32(kd + 16384 + sw), vs + go);
            }
            CP_COMMIT();
            asm volatile("cp.async.wait_group 1;" ::: "memory");
        } else {
            asm volatile("cp.async.wait_group 0;" ::: "memory");
        }
        __syncthreads();

        if (kt == 0) {
            uint32_t qbase = smem_u32(smem);
            #pragma unroll
            for (int kk = 0; kk < 4; kk++) {
                int arow = w * 16 + (lane & 15);
                uint32_t off = arow * 128 + (((kk * 2 + (lane >> 4)) ^ (arow & 7)) * 16);
                ldsm4(qa[kk][0], qa[kk][1], qa[kk][2], qa[kk][3], qbase + off);
            }
        }

        uint32_t kbase = smem_u32(smem + 16384 + (kt & 1) * 32768);
        uint32_t vbase = kbase + 16384;

        // ---- S = Q K^T ----
        float sacc[16][4];
        #pragma unroll
        for (int j = 0; j < 16; j++)
            #pragma unroll
            for (int r = 0; r < 4; r++) sacc[j][r] = 0.f;

        #pragma unroll
        for (int kk = 0; kk < 4; kk++) {
            #pragma unroll
            for (int jp = 0; jp < 8; jp++) {
                int brow = (jp * 2 + (lane >> 4)) * 8 + (lane & 7);
                int sub = (lane >> 3) & 1;
                uint32_t off = brow * 128 + (((kk * 2 + sub) ^ (brow & 7)) * 16);
                uint32_t bb[4];
                ldsm4(bb[0], bb[1], bb[2], bb[3], kbase + off);
                mma_f16(sacc[jp * 2], qa[kk], bb);
                mma_f16(sacc[jp * 2 + 1], qa[kk], bb + 2);
            }
        }

        // ---- online softmax (base 2) ----
        float mt1 = -INFINITY, mt2 = -INFINITY;
        #pragma unroll
        for (int j = 0; j < 16; j++) {
            mt1 = fmaxf(mt1, fmaxf(sacc[j][0], sacc[j][1]));
            mt2 = fmaxf(mt2, fmaxf(sacc[j][2], sacc[j][3]));
        }
        mt1 = fmaxf(mt1, __shfl_xor_sync(0xffffffffu, mt1, 1));
        mt1 = fmaxf(mt1, __shfl_xor_sync(0xffffffffu, mt1, 2));
        mt2 = fmaxf(mt2, __shfl_xor_sync(0xffffffffu, mt2, 1));
        mt2 = fmaxf(mt2, __shfl_xor_sync(0xffffffffu, mt2, 2));
        float mn1 = fmaxf(m1, mt1), mn2 = fmaxf(m2, mt2);
        float al1 = ex2f(m1 - mn1), al2 = ex2f(m2 - mn2);
        m1 = mn1; m2 = mn2;

        uint32_t ph[16], ph2[16];
        float ls1 = 0.f, ls2 = 0.f;
        #pragma unroll
        for (int j = 0; j < 16; j++) {
            float p0 = ex2f(sacc[j][0] - mn1);
            float p1 = ex2f(sacc[j][1] - mn1);
            float p2 = ex2f(sacc[j][2] - mn2);
            float p3 = ex2f(sacc[j][3] - mn2);
            ls1 += p0 + p1;
            ls2 += p2 + p3;
            ph[j]  = pack_h2(p0, p1);
            ph2[j] = pack_h2(p2, p3);
        }
        l1 = l1 * al1 + ls1;
        l2 = l2 * al2 + ls2;
        #pragma unroll
        for (int j = 0; j < 8; j++) {
            oacc[j][0] *= al1; oacc[j][1] *= al1;
            oacc[j][2] *= al2; oacc[j][3] *= al2;
        }

        // ---- O += P V ----
        #pragma unroll
        for (int kk2 = 0; kk2 < 8; kk2++) {
            uint32_t pa[4] = {ph[kk2 * 2], ph2[kk2 * 2], ph[kk2 * 2 + 1], ph2[kk2 * 2 + 1]};
            #pragma unroll
            for (int jp2 = 0; jp2 < 4; jp2++) {
                int srow = kk2 * 16 + ((lane >> 3) & 1) * 8 + (lane & 7);
                int ch = jp2 * 2 + (lane >> 4);
                uint32_t off = srow * 128 + ((ch ^ (srow & 7)) * 16);
                uint32_t bb[4];
                ldsm4t(bb[0], bb[1], bb[2], bb[3], vbase + off);
                mma_f16(oacc[jp2 * 2], pa, bb);
                mma_f16(oacc[jp2 * 2 + 1], pa, bb + 2);
            }
        }
    }

    // ---- epilogue: o = oacc / l, f16 out ----
    l1 += __shfl_xor_sync(0xffffffffu, l1, 1);
    l1 += __shfl_xor_sync(0xffffffffu, l1, 2);
    l2 += __shfl_xor_sync(0xffffffffu, l2, 1);
    l2 += __shfl_xor_sync(0xffffffffu, l2, 2);
    float inv1 = 1.0f / l1, inv2 = 1.0f / l2;

    int r1 = t0 + w * 16 + (lane >> 2);
    int r2 = r1 + 8;
    size_t row1 = (size_t)(b * 1024 + r1) * EMB + h * HEAD_SZ;
    size_t row2 = (size_t)(b * 1024 + r2) * EMB + h * HEAD_SZ;
    #pragma unroll
    for (int j = 0; j < 8; j++) {
        int d = j * 8 + (lane & 3) * 2;
        __half2 p1v = __floats2half2_rn(oacc[j][0] * inv1, oacc[j][1] * inv1);
        __half2 p2v = __floats2half2_rn(oacc[j][2] * inv2, oacc[j][3] * inv2);
        *(__half2*)(g_a16 + row1 + d) = p1v;
        *(__half2*)(g_a16 + row2 + d) = p2v;
    }
}

// ================= launch =================
extern "C" void kernel_launch(void* const* d_in, const int* in_sizes, int n_in,
                              void* d_out, int out_size) {
    const float* x      = (const float*)d_in[0];
    const float* wq     = (const float*)d_in[1];
    const float* wk     = (const float*)d_in[2];
    const float* wv     = (const float*)d_in[3];
    const float* w_proj = (const float*)d_in[4];
    const float* b_proj = (const float*)d_in[5];
    const float* w1     = (const float*)d_in[6];
    const float* b1     = (const float*)d_in[7];
    const float* w2     = (const float*)d_in[8];
    const float* b2     = (const float*)d_in[9];
    const float* g1     = (const float*)d_in[10];
    const float* be1    = (const float*)d_in[11];
    const float* g2     = (const float*)d_in[12];
    const float* be2    = (const float*)d_in[13];
    float* out = (float*)d_out;

    float *px1, *pt;
    __half *pq16, *pa16, *pu16, *pwqkv, *pwp, *pw1, *pw2;
    cudaGetSymbolAddress((void**)&pq16,  g_qkv16);
    cudaGetSymbolAddress((void**)&pa16,  g_a16);
    cudaGetSymbolAddress((void**)&pu16,  g_u16);
    cudaGetSymbolAddress((void**)&px1,   g_x1);
    cudaGetSymbolAddress((void**)&pt,    g_t);
    cudaGetSymbolAddress((void**)&pwqkv, g_wqkv16);
    cudaGetSymbolAddress((void**)&pwp,   g_wp16);
    cudaGetSymbolAddress((void**)&pw1,   g_w116);
    cudaGetSymbolAddress((void**)&pw2,   g_w216);

    cudaFuncSetAttribute(gemm_mma_kernel<false, false, false, 2>,
                         cudaFuncAttributeMaxDynamicSharedMemorySize, G_SMEM);
    cudaFuncSetAttribute(gemm_mma_kernel<true, false, true, 0>,
                         cudaFuncAttributeMaxDynamicSharedMemorySize, G_SMEM);
    cudaFuncSetAttribute(gemm_mma_kernel<true, true, false, 1>,
                         cudaFuncAttributeMaxDynamicSharedMemorySize, G_SMEM);
    cudaFuncSetAttribute(attn_mma_kernel,
                         cudaFuncAttributeMaxDynamicSharedMemorySize, ATT_SMEM);

    dim3 tb(32, 8);
    // --- weight prep ---
    pack_qkv_tiled<<<dim3(EMB / 32, HEAD_SZ / 32, 48), tb>>>(wq, wk, wv);
    tconv_w_tiled<<<dim3(EMB / 32, EMB / 32), tb>>>(w_proj, pwp, EMB, EMB);
    tconv_w_tiled<<<dim3(FFD / 32, EMB / 32), tb>>>(w1, pw1, EMB, FFD);
    tconv_w_tiled<<<dim3(EMB / 32, FFD / 32), tb>>>(w2, pw2, FFD, EMB);

    // --- h = LN1(x) -> f16 ---
    ln_f16_kernel<<<BT, 256>>>(x, g1, be1, pa16);
    // --- qkv = h @ Wqkv (f16 out, q pre-scaled) ---
    gemm_mma_kernel<false, false, false, 2><<<dim3(N_QKV / 128, BT / 128), 256, G_SMEM>>>(
        pa16, pwqkv, nullptr, nullptr, nullptr, pq16, BT, N_QKV, EMB);
    // --- attention (writes f16 o to a16) ---
    attn_mma_kernel<<<dim3(8, HEADS, 4), 256, ATT_SMEM>>>(pq16);
    // --- x1 = x + o @ Wproj + b_proj (fp32) ---
    gemm_mma_kernel<true, false, true, 0><<<dim3(EMB / 128, BT / 128), 256, G_SMEM>>>(
        pa16, pwp, b_proj, x, px1, nullptr, BT, EMB, EMB);
    // --- t = LN(x1); t2 = LN(t) -> f16 ---
    ln_kernel<<<BT, 256>>>(px1, g2, be2, pt);
    ln_f16_kernel<<<BT, 256>>>(pt, g2, be2, pa16);
    // --- u = relu(t2 @ W1 + b1) -> f16 ---
    gemm_mma_kernel<true, true, false, 1><<<dim3(FFD / 128, BT / 128), 256, G_SMEM>>>(
        pa16, pw1, b1, nullptr, nullptr, pu16, BT, FFD, EMB);
    // --- out = x1 + u @ W2 + b2 (fp32) ---
    gemm_mma_kernel<true, false, true, 0><<<dim3(EMB / 128, BT / 128), 256, G_SMEM>>>(
        pu16, pw2, b2, px1, out, nullptr, BT, EMB, FFD);
}

// round 9
// speedup vs baseline: 6.7338x; 1.0068x over previous
#include <cuda_runtime.h>
#include <cuda_bf16.h>
#include <cuda_fp16.h>
#include <math.h>
#include <stdint.h>

#define EMB 1024
#define HEADS 16
#define HEAD_SZ 64
#define BT 4096
#define FFD 4096
#define N_QKV 3072
#define QSCALE 0.18033688011112042f   // log2(e)/8

// ---------------- scratch (static device arrays; no allocation) ----------------
__device__ __half g_qkv16[BT * N_QKV];    // f16 qkv (q pre-scaled)
__device__ __half g_a16  [BT * EMB];      // f16 activations (LN1 out / attn out / LN2 out)
__device__ __half g_u16  [BT * FFD];      // f16 FF hidden
__device__ float  g_x1   [BT * EMB];
// f16 transposed weights, Bt[N][K] layout (K contiguous)
__device__ __half g_wqkv16[N_QKV * EMB];
__device__ __half g_wp16  [EMB * EMB];
__device__ __half g_w116  [FFD * EMB];
__device__ __half g_w216  [EMB * FFD];

// ================= helpers =================
__device__ __forceinline__ uint32_t smem_u32(const void* p) {
    uint32_t a;
    asm("{ .reg .u64 t; cvta.to.shared.u64 t, %1; cvt.u32.u64 %0, t; }" : "=r"(a) : "l"(p));
    return a;
}
__device__ __forceinline__ void ldsm4(uint32_t& a, uint32_t& b, uint32_t& c, uint32_t& d,
                                      uint32_t addr) {
    asm volatile("ldmatrix.sync.aligned.m8n8.x4.shared.b16 {%0,%1,%2,%3}, [%4];"
                 : "=r"(a), "=r"(b), "=r"(c), "=r"(d) : "r"(addr));
}
__device__ __forceinline__ void ldsm4t(uint32_t& a, uint32_t& b, uint32_t& c, uint32_t& d,
                                       uint32_t addr) {
    asm volatile("ldmatrix.sync.aligned.m8n8.x4.trans.shared.b16 {%0,%1,%2,%3}, [%4];"
                 : "=r"(a), "=r"(b), "=r"(c), "=r"(d) : "r"(addr));
}
__device__ __forceinline__ void mma_f16(float* c, const uint32_t* a, const uint32_t* b) {
    asm volatile("mma.sync.aligned.m16n8k16.row.col.f32.f16.f16.f32 "
                 "{%0,%1,%2,%3}, {%4,%5,%6,%7}, {%8,%9}, {%0,%1,%2,%3};"
                 : "+f"(c[0]), "+f"(c[1]), "+f"(c[2]), "+f"(c[3])
                 : "r"(a[0]), "r"(a[1]), "r"(a[2]), "r"(a[3]), "r"(b[0]), "r"(b[1]));
}
__device__ __forceinline__ void cp_async16(uint32_t dst, const void* src) {
    asm volatile("cp.async.cg.shared.global [%0], [%1], 16;" :: "r"(dst), "l"(src));
}
#define CP_COMMIT() asm volatile("cp.async.commit_group;" ::: "memory")

__device__ __forceinline__ float ex2f(float x) {
    float r;
    asm("ex2.approx.f32 %0, %1;" : "=f"(r) : "f"(x));
    return r;
}
__device__ __forceinline__ uint32_t pack_h2(float a, float b) {
    __half2 h = __floats2half2_rn(a, b);
    return *(uint32_t*)&h;
}

// ================= weight prep kernels =================
// tiled transpose+convert: W[K,N] -> Wt[N,K] f16. block (32,8), grid (N/32, K/32)
__global__ void tconv_w_tiled(const float* __restrict__ W,
                              __half* __restrict__ o16, int K, int N) {
    __shared__ float tile[32][33];
    int nb = blockIdx.x * 32, kb = blockIdx.y * 32;
    int tx = threadIdx.x, ty = threadIdx.y;
    #pragma unroll
    for (int i = 0; i < 4; i++)
        tile[ty + i * 8][tx] = W[(size_t)(kb + ty + i * 8) * N + nb + tx];
    __syncthreads();
    #pragma unroll
    for (int i = 0; i < 4; i++) {
        size_t o = (size_t)(nb + ty + i * 8) * K + kb + tx;
        o16[o] = __float2half(tile[tx][ty + i * 8]);
    }
}

// pack+transpose+convert qkv: w[h][c][d] -> Bt[n=sel*1024+h*64+d][k=c] f16
__global__ void pack_qkv_tiled(const float* __restrict__ wq,
                               const float* __restrict__ wk,
                               const float* __restrict__ wv) {
    __shared__ float tile[32][33];
    int hz = blockIdx.z;
    int sel = hz >> 4, h = hz & 15;
    const float* w = (sel == 0) ? wq : (sel == 1) ? wk : wv;
    int c0 = blockIdx.x * 32, d0 = blockIdx.y * 32;
    int tx = threadIdx.x, ty = threadIdx.y;
    const float* base = w + (size_t)h * EMB * HEAD_SZ;
    #pragma unroll
    for (int i = 0; i < 4; i++)
        tile[ty + i * 8][tx] = base[(size_t)(c0 + ty + i * 8) * HEAD_SZ + d0 + tx];
    __syncthreads();
    #pragma unroll
    for (int i = 0; i < 4; i++) {
        size_t n = (size_t)sel * 1024 + h * 64 + d0 + ty + i * 8;
        g_wqkv16[n * EMB + c0 + tx] = __float2half(tile[tx][ty + i * 8]);
    }
}

// ================= LayerNorm variants =================
__device__ __forceinline__ void ln_stats(float4 xv, int tid, float& mu, float& rstd) {
    float s  = xv.x + xv.y + xv.z + xv.w;
    float ss = xv.x*xv.x + xv.y*xv.y + xv.z*xv.z + xv.w*xv.w;
    #pragma unroll
    for (int o = 16; o; o >>= 1) {
        s  += __shfl_xor_sync(0xffffffffu, s,  o);
        ss += __shfl_xor_sync(0xffffffffu, ss, o);
    }
    __shared__ float rs[8], rss[8];
    int wid = tid >> 5, lane = tid & 31;
    if (!lane) { rs[wid] = s; rss[wid] = ss; }
    __syncthreads();
    s = 0.f; ss = 0.f;
    #pragma unroll
    for (int i = 0; i < 8; i++) { s += rs[i]; ss += rss[i]; }
    mu = s * (1.0f / EMB);
    float var = ss * (1.0f / EMB) - mu * mu;
    rstd = rsqrtf(var + 1e-5f);
}

// single LN -> f16
__global__ __launch_bounds__(256) void ln_f16_kernel(const float* __restrict__ in,
                                                     const float* __restrict__ gw,
                                                     const float* __restrict__ bw,
                                                     __half* __restrict__ o16) {
    int row = blockIdx.x;
    int tid = threadIdx.x;
    float4 xv = ((const float4*)(in + (size_t)row * EMB))[tid];
    float mu, rstd;
    ln_stats(xv, tid, mu, rstd);
    float4 gv = ((const float4*)gw)[tid];
    float4 bv = ((const float4*)bw)[tid];
    __half2 p0 = __floats2half2_rn((xv.x - mu) * rstd * gv.x + bv.x,
                                   (xv.y - mu) * rstd * gv.y + bv.y);
    __half2 p1 = __floats2half2_rn((xv.z - mu) * rstd * gv.z + bv.z,
                                   (xv.w - mu) * rstd * gv.w + bv.w);
    uint2 pk; pk.x = *(uint32_t*)&p0; pk.y = *(uint32_t*)&p1;
    *(uint2*)(o16 + (size_t)row * EMB + tid * 4) = pk;
}

// fused LN(LN(x)) -> f16 (faithful double-LN of the reference)
__global__ __launch_bounds__(256) void ln2_f16_kernel(const float* __restrict__ in,
                                                      const float* __restrict__ gw,
                                                      const float* __restrict__ bw,
                                                      __half* __restrict__ o16) {
    int row = blockIdx.x;
    int tid = threadIdx.x;
    float4 xv = ((const float4*)(in + (size_t)row * EMB))[tid];
    float mu, rstd;
    ln_stats(xv, tid, mu, rstd);
    float4 gv = ((const float4*)gw)[tid];
    float4 bv = ((const float4*)bw)[tid];
    float4 y;
    y.x = (xv.x - mu) * rstd * gv.x + bv.x;
    y.y = (xv.y - mu) * rstd * gv.y + bv.y;
    y.z = (xv.z - mu) * rstd * gv.z + bv.z;
    y.w = (xv.w - mu) * rstd * gv.w + bv.w;
    __syncthreads();     // protect shared reduction buffers between the two passes
    float mu2, rstd2;
    ln_stats(y, tid, mu2, rstd2);
    __half2 p0 = __floats2half2_rn((y.x - mu2) * rstd2 * gv.x + bv.x,
                                   (y.y - mu2) * rstd2 * gv.y + bv.y);
    __half2 p1 = __floats2half2_rn((y.z - mu2) * rstd2 * gv.z + bv.z,
                                   (y.w - mu2) * rstd2 * gv.w + bv.w);
    uint2 pk; pk.x = *(uint32_t*)&p0; pk.y = *(uint32_t*)&p1;
    *(uint2*)(o16 + (size_t)row * EMB + tid * 4) = pk;
}

// ================= mma.sync GEMM (single-pass f16, 3-stage pipeline) =================
// C[M,N] = A[M,K] @ Bt[N,K]^T. CTA 128x128, BK=64, 3-stage cp.async, 1 sync/iter.
// 8 warps: warp tile 64(m) x 32(n). 128B-row XOR swizzle in smem.
// OMODE: 0 = fp32 C, 1 = f16 out, 2 = f16 qkv out (q cols pre-scaled)
#define GT 16384
#define GSTAGE (2 * GT)
#define G_SMEM (3 * GSTAGE)     // 96 KB

template<bool BIAS, bool RELU, bool RES, int OMODE>
__global__ __launch_bounds__(256, 1) void gemm_mma_kernel(
    const __half* __restrict__ A, const __half* __restrict__ B,
    const float* __restrict__ bias, const float* __restrict__ res,
    float* __restrict__ C, __half* __restrict__ O16,
    int M, int N, int K)
{
    extern __shared__ __align__(1024) char smem[];
    int tid = threadIdx.x, lane = tid & 31, wid = tid >> 5;
    int m0 = blockIdx.y * 128, n0 = blockIdx.x * 128;
    int wm = (wid >> 2) * 64, wn = (wid & 3) * 32;

    const __half* srcs[2] = {A + (size_t)m0 * K, B + (size_t)n0 * K};
    int fr[4], fc[4];
    #pragma unroll
    for (int i = 0; i < 4; i++) {
        int flat = i * 256 + tid;
        fr[i] = flat >> 3;
        fc[i] = flat & 7;
    }

    int nst = K >> 6;

    auto issue = [&](int st) {
        char* buf = smem + (st % 3) * GSTAGE;
        int ko = st * 64;
        #pragma unroll
        for (int t = 0; t < 2; t++)
            #pragma unroll
            for (int i = 0; i < 4; i++) {
                uint32_t sw = fr[i] * 128 + ((fc[i] ^ (fr[i] & 7)) * 16);
                cp_async16(smem_u32(buf + t * GT + sw),
                           srcs[t] + (size_t)fr[i] * K + ko + fc[i] * 8);
            }
        CP_COMMIT();
    };

    issue(0);
    if (nst > 1) issue(1);

    float acc[4][4][4];
    #pragma unroll
    for (int i = 0; i < 4; i++)
        #pragma unroll
        for (int j = 0; j < 4; j++)
            #pragma unroll
            for (int r = 0; r < 4; r++) acc[i][j][r] = 0.f;

    for (int kt = 0; kt < nst; kt++) {
        if (kt + 1 < nst) asm volatile("cp.async.wait_group 1;" ::: "memory");
        else              asm volatile("cp.async.wait_group 0;" ::: "memory");
        __syncthreads();
        if (kt + 2 < nst) issue(kt + 2);

        char* buf = smem + (kt % 3) * GSTAGE;
        uint32_t aB = smem_u32(buf);
        uint32_t bB = aB + GT;

        #pragma unroll
        for (int kk = 0; kk < 4; kk++) {
            uint32_t ah[4][4];
            #pragma unroll
            for (int i = 0; i < 4; i++) {
                int arow = wm + i * 16 + (lane & 15);
                uint32_t off = arow * 128 + (((kk * 2 + (lane >> 4)) ^ (arow & 7)) * 16);
                ldsm4(ah[i][0], ah[i][1], ah[i][2], ah[i][3], aB + off);
            }
            uint32_t bh[4][2];
            #pragma unroll
            for (int jp = 0; jp < 2; jp++) {
                int brow = wn + (jp * 2 + (lane >> 4)) * 8 + (lane & 7);
                int sub = (lane >> 3) & 1;
                uint32_t off = brow * 128 + (((kk * 2 + sub) ^ (brow & 7)) * 16);
                uint32_t r0, r1, r2, r3;
                ldsm4(r0, r1, r2, r3, bB + off);
                bh[jp * 2][0] = r0; bh[jp * 2][1] = r1;
                bh[jp * 2 + 1][0] = r2; bh[jp * 2 + 1][1] = r3;
            }
            #pragma unroll
            for (int i = 0; i < 4; i++)
                #pragma unroll
                for (int j = 0; j < 4; j++)
                    mma_f16(acc[i][j], ah[i], bh[j]);
        }
    }

    // epilogue
    float qsc = 1.0f;
    if (OMODE == 2) qsc = (n0 < 1024) ? QSCALE : 1.0f;
    int r_lo = lane >> 2, c_lo = (lane & 3) * 2;
    #pragma unroll
    for (int i = 0; i < 4; i++)
        #pragma unroll
        for (int rr = 0; rr < 2; rr++) {
            int m = m0 + wm + i * 16 + r_lo + rr * 8;
            const float* rrow = RES ? (res + (size_t)m * N) : (const float*)0;
            #pragma unroll
            for (int j = 0; j < 4; j++) {
                int n = n0 + wn + j * 8 + c_lo;
                float2 v = make_float2(acc[i][j][rr * 2], acc[i][j][rr * 2 + 1]);
                if (BIAS) {
                    float2 b2v = *(const float2*)(bias + n);
                    v.x += b2v.x; v.y += b2v.y;
                }
                if (RELU) { v.x = fmaxf(v.x, 0.f); v.y = fmaxf(v.y, 0.f); }
                if (RES) {
                    float2 r2v = *(const float2*)(rrow + n);
                    v.x += r2v.x; v.y += r2v.y;
                }
                if (OMODE == 0) {
                    *(float2*)(C + (size_t)m * N + n) = v;
                } else {
                    float s = (OMODE == 2) ? qsc : 1.0f;
                    __half2 hp = __floats2half2_rn(v.x * s, v.y * s);
                    *(__half2*)(O16 + (size_t)m * N + n) = hp;
                }
            }
        }
}

// ================= f16 mma flash attention (3-stage KV pipeline) =================
// grid (8 q-tiles, 16 heads, 4 batch), 256 threads (8 warps), warp = 16 q rows.
// smem: Q 16K | 3 x (K 16K + V 16K) = 112 KB
#define ATT_SMEM (112 * 1024)

__global__ __launch_bounds__(256) void attn_mma_kernel(const __half* __restrict__ qkv) {
    extern __shared__ __align__(1024) char smem[];
    int tid = threadIdx.x, lane = tid & 31, w = tid >> 5;
    int tile = blockIdx.x, h = blockIdx.y, b = blockIdx.z;
    int t0 = tile * 128;

    const __half* qb = qkv + (size_t)(b * 1024 + t0) * N_QKV + h * HEAD_SZ;
    const __half* kb = qkv + (size_t)(b * 1024) * N_QKV + 1024 + h * HEAD_SZ;
    const __half* vb = qkv + (size_t)(b * 1024) * N_QKV + 2048 + h * HEAD_SZ;

    int fr[4], fc[4];
    #pragma unroll
    for (int i = 0; i < 4; i++) {
        int flat = i * 256 + tid;
        fr[i] = flat >> 3;
        fc[i] = flat & 7;
    }

    auto issue_kv = [&](int st) {
        const __half* ks = kb + (size_t)st * 128 * N_QKV;
        const __half* vs = vb + (size_t)st * 128 * N_QKV;
        char* kd = smem + 16384 + (st % 3) * 32768;
        #pragma unroll
        for (int i = 0; i < 4; i++) {
            uint32_t sw = fr[i] * 128 + ((fc[i] ^ (fr[i] & 7)) * 16);
            size_t go = (size_t)fr[i] * N_QKV + fc[i] * 8;
            cp_async16(smem_u32(kd + sw), ks + go);
            cp_async16(smem_u32(kd + 16384 + sw), vs + go);
        }
        CP_COMMIT();
    };

    // prologue: Q (+K0+V0 in the same group), then K1+V1
    #pragma unroll
    for (int i = 0; i < 4; i++) {
        uint32_t sw = fr[i] * 128 + ((fc[i] ^ (fr[i] & 7)) * 16);
        cp_async16(smem_u32(smem + sw), qb + (size_t)fr[i] * N_QKV + fc[i] * 8);
    }
    issue_kv(0);
    issue_kv(1);

    uint32_t qa[4][4];
    float m1 = -INFINITY, m2 = -INFINITY, l1 = 0.f, l2 = 0.f;
    float oacc[8][4];
    #pragma unroll
    for (int j = 0; j < 8; j++)
        #pragma unroll
        for (int r = 0; r < 4; r++) oacc[j][r] = 0.f;

    for (int kt = 0; kt < 8; kt++) {
        if (kt < 7) asm volatile("cp.async.wait_group 1;" ::: "memory");
        else        asm volatile("cp.async.wait_group 0;" ::: "memory");
        __syncthreads();
        if (kt + 2 < 8) issue_kv(kt + 2);

        if (kt == 0) {
            uint32_t qbase = smem_u32(smem);
            #pragma unroll
            for (int kk = 0; kk < 4; kk++) {
                int arow = w * 16 + (lane & 15);
                uint32_t off = arow * 128 + (((kk * 2 + (lane >> 4)) ^ (arow & 7)) * 16);
                ldsm4(qa[kk][0], qa[kk][1], qa[kk][2], qa[kk][3], qbase + off);
            }
        }

        uint32_t kbase = smem_u32(smem + 16384 + (kt % 3) * 32768);
        uint32_t vbase = kbase + 16384;

        // ---- S = Q K^T ----
        float sacc[16][4];
        #pragma unroll
        for (int j = 0; j < 16; j++)
            #pragma unroll
            for (int r = 0; r < 4; r++) sacc[j][r] = 0.f;

        #pragma unroll
        for (int kk = 0; kk < 4; kk++) {
            #pragma unroll
            for (int jp = 0; jp < 8; jp++) {
                int brow = (jp * 2 + (lane >> 4)) * 8 + (lane & 7);
                int sub = (lane >> 3) & 1;
                uint32_t off = brow * 128 + (((kk * 2 + sub) ^ (brow & 7)) * 16);
                uint32_t bb[4];
                ldsm4(bb[0], bb[1], bb[2], bb[3], kbase + off);
                mma_f16(sacc[jp * 2], qa[kk], bb);
                mma_f16(sacc[jp * 2 + 1], qa[kk], bb + 2);
            }
        }

        // ---- online softmax (base 2) ----
        float mt1 = -INFINITY, mt2 = -INFINITY;
        #pragma unroll
        for (int j = 0; j < 16; j++) {
            mt1 = fmaxf(mt1, fmaxf(sacc[j][0], sacc[j][1]));
            mt2 = fmaxf(mt2, fmaxf(sacc[j][2], sacc[j][3]));
        }
        mt1 = fmaxf(mt1, __shfl_xor_sync(0xffffffffu, mt1, 1));
        mt1 = fmaxf(mt1, __shfl_xor_sync(0xffffffffu, mt1, 2));
        mt2 = fmaxf(mt2, __shfl_xor_sync(0xffffffffu, mt2, 1));
        mt2 = fmaxf(mt2, __shfl_xor_sync(0xffffffffu, mt2, 2));
        float mn1 = fmaxf(m1, mt1), mn2 = fmaxf(m2, mt2);
        float al1 = ex2f(m1 - mn1), al2 = ex2f(m2 - mn2);
        m1 = mn1; m2 = mn2;

        uint32_t ph[16], ph2[16];
        float ls1 = 0.f, ls2 = 0.f;
        #pragma unroll
        for (int j = 0; j < 16; j++) {
            float p0 = ex2f(sacc[j][0] - mn1);
            float p1 = ex2f(sacc[j][1] - mn1);
            float p2 = ex2f(sacc[j][2] - mn2);
            float p3 = ex2f(sacc[j][3] - mn2);
            ls1 += p0 + p1;
            ls2 += p2 + p3;
            ph[j]  = pack_h2(p0, p1);
            ph2[j] = pack_h2(p2, p3);
        }
        l1 = l1 * al1 + ls1;
        l2 = l2 * al2 + ls2;
        #pragma unroll
        for (int j = 0; j < 8; j++) {
            oacc[j][0] *= al1; oacc[j][1] *= al1;
            oacc[j][2] *= al2; oacc[j][3] *= al2;
        }

        // ---- O += P V ----
        #pragma unroll
        for (int kk2 = 0; kk2 < 8; kk2++) {
            uint32_t pa[4] = {ph[kk2 * 2], ph2[kk2 * 2], ph[kk2 * 2 + 1], ph2[kk2 * 2 + 1]};
            #pragma unroll
            for (int jp2 = 0; jp2 < 4; jp2++) {
                int srow = kk2 * 16 + ((lane >> 3) & 1) * 8 + (lane & 7);
                int ch = jp2 * 2 + (lane >> 4);
                uint32_t off = srow * 128 + ((ch ^ (srow & 7)) * 16);
                uint32_t bb[4];
                ldsm4t(bb[0], bb[1], bb[2], bb[3], vbase + off);
                mma_f16(oacc[jp2 * 2], pa, bb);
                mma_f16(oacc[jp2 * 2 + 1], pa, bb + 2);
            }
        }
    }

    // ---- epilogue: o = oacc / l, f16 out ----
    l1 += __shfl_xor_sync(0xffffffffu, l1, 1);
    l1 += __shfl_xor_sync(0xffffffffu, l1, 2);
    l2 += __shfl_xor_sync(0xffffffffu, l2, 1);
    l2 += __shfl_xor_sync(0xffffffffu, l2, 2);
    float inv1 = 1.0f / l1, inv2 = 1.0f / l2;

    int r1 = t0 + w * 16 + (lane >> 2);
    int r2 = r1 + 8;
    size_t row1 = (size_t)(b * 1024 + r1) * EMB + h * HEAD_SZ;
    size_t row2 = (size_t)(b * 1024 + r2) * EMB + h * HEAD_SZ;
    #pragma unroll
    for (int j = 0; j < 8; j++) {
        int d = j * 8 + (lane & 3) * 2;
        __half2 p1v = __floats2half2_rn(oacc[j][0] * inv1, oacc[j][1] * inv1);
        __half2 p2v = __floats2half2_rn(oacc[j][2] * inv2, oacc[j][3] * inv2);
        *(__half2*)(g_a16 + row1 + d) = p1v;
        *(__half2*)(g_a16 + row2 + d) = p2v;
    }
}

// ================= launch =================
extern "C" void kernel_launch(void* const* d_in, const int* in_sizes, int n_in,
                              void* d_out, int out_size) {
    const float* x      = (const float*)d_in[0];
    const float* wq     = (const float*)d_in[1];
    const float* wk     = (const float*)d_in[2];
    const float* wv     = (const float*)d_in[3];
    const float* w_proj = (const float*)d_in[4];
    const float* b_proj = (const float*)d_in[5];
    const float* w1     = (const float*)d_in[6];
    const float* b1     = (const float*)d_in[7];
    const float* w2     = (const float*)d_in[8];
    const float* b2     = (const float*)d_in[9];
    const float* g1     = (const float*)d_in[10];
    const float* be1    = (const float*)d_in[11];
    const float* g2     = (const float*)d_in[12];
    const float* be2    = (const float*)d_in[13];
    float* out = (float*)d_out;

    float* px1;
    __half *pq16, *pa16, *pu16, *pwqkv, *pwp, *pw1, *pw2;
    cudaGetSymbolAddress((void**)&pq16,  g_qkv16);
    cudaGetSymbolAddress((void**)&pa16,  g_a16);
    cudaGetSymbolAddress((void**)&pu16,  g_u16);
    cudaGetSymbolAddress((void**)&px1,   g_x1);
    cudaGetSymbolAddress((void**)&pwqkv, g_wqkv16);
    cudaGetSymbolAddress((void**)&pwp,   g_wp16);
    cudaGetSymbolAddress((void**)&pw1,   g_w116);
    cudaGetSymbolAddress((void**)&pw2,   g_w216);

    cudaFuncSetAttribute(gemm_mma_kernel<false, false, false, 2>,
                         cudaFuncAttributeMaxDynamicSharedMemorySize, G_SMEM);
    cudaFuncSetAttribute(gemm_mma_kernel<true, false, true, 0>,
                         cudaFuncAttributeMaxDynamicSharedMemorySize, G_SMEM);
    cudaFuncSetAttribute(gemm_mma_kernel<true, true, false, 1>,
                         cudaFuncAttributeMaxDynamicSharedMemorySize, G_SMEM);
    cudaFuncSetAttribute(attn_mma_kernel,
                         cudaFuncAttributeMaxDynamicSharedMemorySize, ATT_SMEM);

    dim3 tb(32, 8);
    // --- weight prep ---
    pack_qkv_tiled<<<dim3(EMB / 32, HEAD_SZ / 32, 48), tb>>>(wq, wk, wv);
    tconv_w_tiled<<<dim3(EMB / 32, EMB / 32), tb>>>(w_proj, pwp, EMB, EMB);
    tconv_w_tiled<<<dim3(FFD / 32, EMB / 32), tb>>>(w1, pw1, EMB, FFD);
    tconv_w_tiled<<<dim3(EMB / 32, FFD / 32), tb>>>(w2, pw2, FFD, EMB);

    // --- h = LN1(x) -> f16 ---
    ln_f16_kernel<<<BT, 256>>>(x, g1, be1, pa16);
    // --- qkv = h @ Wqkv (f16 out, q pre-scaled) ---
    gemm_mma_kernel<false, false, false, 2><<<dim3(N_QKV / 128, BT / 128), 256, G_SMEM>>>(
        pa16, pwqkv, nullptr, nullptr, nullptr, pq16, BT, N_QKV, EMB);
    // --- attention (writes f16 o to a16) ---
    attn_mma_kernel<<<dim3(8, HEADS, 4), 256, ATT_SMEM>>>(pq16);
    // --- x1 = x + o @ Wproj + b_proj (fp32) ---
    gemm_mma_kernel<true, false, true, 0><<<dim3(EMB / 128, BT / 128), 256, G_SMEM>>>(
        pa16, pwp, b_proj, x, px1, nullptr, BT, EMB, EMB);
    // --- t2 = LN(LN(x1)) -> f16 (fused double-LN) ---
    ln2_f16_kernel<<<BT, 256>>>(px1, g2, be2, pa16);
    // --- u = relu(t2 @ W1 + b1) -> f16 ---
    gemm_mma_kernel<true, true, false, 1><<<dim3(FFD / 128, BT / 128), 256, G_SMEM>>>(
        pa16, pw1, b1, nullptr, nullptr, pu16, BT, FFD, EMB);
    // --- out = x1 + u @ W2 + b2 (fp32) ---
    gemm_mma_kernel<true, false, true, 0><<<dim3(EMB / 128, BT / 128), 256, G_SMEM>>>(
        pu16, pw2, b2, px1, out, nullptr, BT, EMB, FFD);
}

// round 11
// speedup vs baseline: 7.0673x; 1.0495x over previous
#include <cuda_runtime.h>
#include <cuda_bf16.h>
#include <cuda_fp16.h>
#include <math.h>
#include <stdint.h>

#define EMB 1024
#define HEADS 16
#define HEAD_SZ 64
#define BT 4096
#define FFD 4096
#define N_QKV 3072
#define QSCALE 0.18033688011112042f   // log2(e)/8

// ---------------- scratch (static device arrays; no allocation) ----------------
__device__ __half g_qkv16[BT * N_QKV];    // f16 qkv (q pre-scaled)
__device__ __half g_a16  [BT * EMB];      // f16 activations
__device__ __half g_u16  [BT * FFD];      // f16 FF hidden
__device__ float  g_x1   [BT * EMB];
// f16 transposed weights, Bt[N][K] layout (K contiguous)
__device__ __half g_wqkv16[N_QKV * EMB];
__device__ __half g_wp16  [EMB * EMB];
__device__ __half g_w116  [FFD * EMB];
__device__ __half g_w216  [EMB * FFD];

// ================= helpers =================
__device__ __forceinline__ uint32_t smem_u32(const void* p) {
    uint32_t a;
    asm("{ .reg .u64 t; cvta.to.shared.u64 t, %1; cvt.u32.u64 %0, t; }" : "=r"(a) : "l"(p));
    return a;
}
__device__ __forceinline__ void ldsm4(uint32_t& a, uint32_t& b, uint32_t& c, uint32_t& d,
                                      uint32_t addr) {
    asm volatile("ldmatrix.sync.aligned.m8n8.x4.shared.b16 {%0,%1,%2,%3}, [%4];"
                 : "=r"(a), "=r"(b), "=r"(c), "=r"(d) : "r"(addr));
}
__device__ __forceinline__ void ldsm4t(uint32_t& a, uint32_t& b, uint32_t& c, uint32_t& d,
                                       uint32_t addr) {
    asm volatile("ldmatrix.sync.aligned.m8n8.x4.trans.shared.b16 {%0,%1,%2,%3}, [%4];"
                 : "=r"(a), "=r"(b), "=r"(c), "=r"(d) : "r"(addr));
}
__device__ __forceinline__ void mma_f16(float* c, const uint32_t* a, const uint32_t* b) {
    asm volatile("mma.sync.aligned.m16n8k16.row.col.f32.f16.f16.f32 "
                 "{%0,%1,%2,%3}, {%4,%5,%6,%7}, {%8,%9}, {%0,%1,%2,%3};"
                 : "+f"(c[0]), "+f"(c[1]), "+f"(c[2]), "+f"(c[3])
                 : "r"(a[0]), "r"(a[1]), "r"(a[2]), "r"(a[3]), "r"(b[0]), "r"(b[1]));
}
__device__ __forceinline__ void cp_async16(uint32_t dst, const void* src) {
    asm volatile("cp.async.cg.shared.global [%0], [%1], 16;" :: "r"(dst), "l"(src));
}
#define CP_COMMIT() asm volatile("cp.async.commit_group;" ::: "memory")

__device__ __forceinline__ float ex2f(float x) {
    float r;
    asm("ex2.approx.f32 %0, %1;" : "=f"(r) : "f"(x));
    return r;
}
__device__ __forceinline__ uint32_t pack_h2(float a, float b) {
    __half2 h = __floats2half2_rn(a, b);
    return *(uint32_t*)&h;
}

// ================= weight prep kernels =================
__global__ void tconv_w_tiled(const float* __restrict__ W,
                              __half* __restrict__ o16, int K, int N) {
    __shared__ float tile[32][33];
    int nb = blockIdx.x * 32, kb = blockIdx.y * 32;
    int tx = threadIdx.x, ty = threadIdx.y;
    #pragma unroll
    for (int i = 0; i < 4; i++)
        tile[ty + i * 8][tx] = W[(size_t)(kb + ty + i * 8) * N + nb + tx];
    __syncthreads();
    #pragma unroll
    for (int i = 0; i < 4; i++) {
        size_t o = (size_t)(nb + ty + i * 8) * K + kb + tx;
        o16[o] = __float2half(tile[tx][ty + i * 8]);
    }
}

__global__ void pack_qkv_tiled(const float* __restrict__ wq,
                               const float* __restrict__ wk,
                               const float* __restrict__ wv) {
    __shared__ float tile[32][33];
    int hz = blockIdx.z;
    int sel = hz >> 4, h = hz & 15;
    const float* w = (sel == 0) ? wq : (sel == 1) ? wk : wv;
    int c0 = blockIdx.x * 32, d0 = blockIdx.y * 32;
    int tx = threadIdx.x, ty = threadIdx.y;
    const float* base = w + (size_t)h * EMB * HEAD_SZ;
    #pragma unroll
    for (int i = 0; i < 4; i++)
        tile[ty + i * 8][tx] = base[(size_t)(c0 + ty + i * 8) * HEAD_SZ + d0 + tx];
    __syncthreads();
    #pragma unroll
    for (int i = 0; i < 4; i++) {
        size_t n = (size_t)sel * 1024 + h * 64 + d0 + ty + i * 8;
        g_wqkv16[n * EMB + c0 + tx] = __float2half(tile[tx][ty + i * 8]);
    }
}

// ================= LayerNorm variants =================
__device__ __forceinline__ void ln_stats(float4 xv, int tid, float& mu, float& rstd) {
    float s  = xv.x + xv.y + xv.z + xv.w;
    float ss = xv.x*xv.x + xv.y*xv.y + xv.z*xv.z + xv.w*xv.w;
    #pragma unroll
    for (int o = 16; o; o >>= 1) {
        s  += __shfl_xor_sync(0xffffffffu, s,  o);
        ss += __shfl_xor_sync(0xffffffffu, ss, o);
    }
    __shared__ float rs[8], rss[8];
    int wid = tid >> 5, lane = tid & 31;
    if (!lane) { rs[wid] = s; rss[wid] = ss; }
    __syncthreads();
    s = 0.f; ss = 0.f;
    #pragma unroll
    for (int i = 0; i < 8; i++) { s += rs[i]; ss += rss[i]; }
    mu = s * (1.0f / EMB);
    float var = ss * (1.0f / EMB) - mu * mu;
    rstd = rsqrtf(var + 1e-5f);
}

__global__ __launch_bounds__(256) void ln_f16_kernel(const float* __restrict__ in,
                                                     const float* __restrict__ gw,
                                                     const float* __restrict__ bw,
                                                     __half* __restrict__ o16) {
    int row = blockIdx.x;
    int tid = threadIdx.x;
    float4 xv = ((const float4*)(in + (size_t)row * EMB))[tid];
    float mu, rstd;
    ln_stats(xv, tid, mu, rstd);
    float4 gv = ((const float4*)gw)[tid];
    float4 bv = ((const float4*)bw)[tid];
    __half2 p0 = __floats2half2_rn((xv.x - mu) * rstd * gv.x + bv.x,
                                   (xv.y - mu) * rstd * gv.y + bv.y);
    __half2 p1 = __floats2half2_rn((xv.z - mu) * rstd * gv.z + bv.z,
                                   (xv.w - mu) * rstd * gv.w + bv.w);
    uint2 pk; pk.x = *(uint32_t*)&p0; pk.y = *(uint32_t*)&p1;
    *(uint2*)(o16 + (size_t)row * EMB + tid * 4) = pk;
}

// fused LN(LN(x)) -> f16
__global__ __launch_bounds__(256) void ln2_f16_kernel(const float* __restrict__ in,
                                                      const float* __restrict__ gw,
                                                      const float* __restrict__ bw,
                                                      __half* __restrict__ o16) {
    int row = blockIdx.x;
    int tid = threadIdx.x;
    float4 xv = ((const float4*)(in + (size_t)row * EMB))[tid];
    float mu, rstd;
    ln_stats(xv, tid, mu, rstd);
    float4 gv = ((const float4*)gw)[tid];
    float4 bv = ((const float4*)bw)[tid];
    float4 y;
    y.x = (xv.x - mu) * rstd * gv.x + bv.x;
    y.y = (xv.y - mu) * rstd * gv.y + bv.y;
    y.z = (xv.z - mu) * rstd * gv.z + bv.z;
    y.w = (xv.w - mu) * rstd * gv.w + bv.w;
    __syncthreads();
    float mu2, rstd2;
    ln_stats(y, tid, mu2, rstd2);
    __half2 p0 = __floats2half2_rn((y.x - mu2) * rstd2 * gv.x + bv.x,
                                   (y.y - mu2) * rstd2 * gv.y + bv.y);
    __half2 p1 = __floats2half2_rn((y.z - mu2) * rstd2 * gv.z + bv.z,
                                   (y.w - mu2) * rstd2 * gv.w + bv.w);
    uint2 pk; pk.x = *(uint32_t*)&p0; pk.y = *(uint32_t*)&p1;
    *(uint2*)(o16 + (size_t)row * EMB + tid * 4) = pk;
}

// ================= mma.sync GEMM (f16, CTA 128x256, warp 64x64, 3-stage) =========
// C[M,N] = A[M,K] @ Bt[N,K]^T. BK=64. 8 warps = 2(m) x 4(n), warp tile 64x64.
// 128B-row XOR swizzle. OMODE: 0 = fp32 C, 1 = f16 out, 2 = f16 qkv (q pre-scaled)
#define GTA 16384                 // A tile: 128 rows x 128B
#define GTB 32768                 // B tile: 256 rows x 128B
#define GSTAGE (GTA + GTB)        // 48 KB
#define G_SMEM (3 * GSTAGE)       // 144 KB

template<bool BIAS, bool RELU, bool RES, int OMODE>
__global__ __launch_bounds__(256, 1) void gemm_mma_kernel(
    const __half* __restrict__ A, const __half* __restrict__ B,
    const float* __restrict__ bias, const float* __restrict__ res,
    float* __restrict__ C, __half* __restrict__ O16,
    int M, int N, int K)
{
    extern __shared__ __align__(1024) char smem[];
    int tid = threadIdx.x, lane = tid & 31, wid = tid >> 5;
    int m0 = blockIdx.y * 128, n0 = blockIdx.x * 256;
    int wm = (wid >> 2) * 64, wn = (wid & 3) * 64;

    const __half* srcA = A + (size_t)m0 * K;
    const __half* srcB = B + (size_t)n0 * K;
    int fr = tid >> 3;            // 0..31 base row step of 32? no: flat rows below
    int fcol = tid & 7;           // 16B chunk 0..7
    (void)fr;

    int nst = K >> 6;

    auto issue = [&](int st) {
        char* buf = smem + (st % 3) * GSTAGE;
        int ko = st * 64;
        // A: 128 rows, 4 chunks per thread
        #pragma unroll
        for (int i = 0; i < 4; i++) {
            int flat = i * 256 + tid;
            int r = flat >> 3, c = flat & 7;
            uint32_t sw = r * 128 + ((c ^ (r & 7)) * 16);
            cp_async16(smem_u32(buf + sw), srcA + (size_t)r * K + ko + c * 8);
        }
        // B: 256 rows, 8 chunks per thread
        #pragma unroll
        for (int i = 0; i < 8; i++) {
            int flat = i * 256 + tid;
            int r = flat >> 3, c = flat & 7;
            uint32_t sw = r * 128 + ((c ^ (r & 7)) * 16);
            cp_async16(smem_u32(buf + GTA + sw), srcB + (size_t)r * K + ko + c * 8);
        }
        CP_COMMIT();
    };

    issue(0);
    if (nst > 1) issue(1);

    float acc[4][8][4];
    #pragma unroll
    for (int i = 0; i < 4; i++)
        #pragma unroll
        for (int j = 0; j < 8; j++)
            #pragma unroll
            for (int r = 0; r < 4; r++) acc[i][j][r] = 0.f;

    for (int kt = 0; kt < nst; kt++) {
        if (kt + 1 < nst) asm volatile("cp.async.wait_group 1;" ::: "memory");
        else              asm volatile("cp.async.wait_group 0;" ::: "memory");
        __syncthreads();
        if (kt + 2 < nst) issue(kt + 2);

        char* buf = smem + (kt % 3) * GSTAGE;
        uint32_t aB = smem_u32(buf);
        uint32_t bB = aB + GTA;

        #pragma unroll
        for (int kk = 0; kk < 4; kk++) {
            uint32_t ah[4][4];
            #pragma unroll
            for (int i = 0; i < 4; i++) {
                int arow = wm + i * 16 + (lane & 15);
                uint32_t off = arow * 128 + (((kk * 2 + (lane >> 4)) ^ (arow & 7)) * 16);
                ldsm4(ah[i][0], ah[i][1], ah[i][2], ah[i][3], aB + off);
            }
            uint32_t bh[8][2];
            #pragma unroll
            for (int jp = 0; jp < 4; jp++) {
                int brow = wn + (jp * 2 + (lane >> 4)) * 8 + (lane & 7);
                int sub = (lane >> 3) & 1;
                uint32_t off = brow * 128 + (((kk * 2 + sub) ^ (brow & 7)) * 16);
                uint32_t r0, r1, r2, r3;
                ldsm4(r0, r1, r2, r3, bB + off);
                bh[jp * 2][0] = r0; bh[jp * 2][1] = r1;
                bh[jp * 2 + 1][0] = r2; bh[jp * 2 + 1][1] = r3;
            }
            #pragma unroll
            for (int i = 0; i < 4; i++)
                #pragma unroll
                for (int j = 0; j < 8; j++)
                    mma_f16(acc[i][j], ah[i], bh[j]);
        }
    }

    // epilogue
    float qsc = 1.0f;
    if (OMODE == 2) qsc = (n0 < 1024) ? QSCALE : 1.0f;
    int r_lo = lane >> 2, c_lo = (lane & 3) * 2;
    #pragma unroll
    for (int i = 0; i < 4; i++)
        #pragma unroll
        for (int rr = 0; rr < 2; rr++) {
            int m = m0 + wm + i * 16 + r_lo + rr * 8;
            const float* rrow = RES ? (res + (size_t)m * N) : (const float*)0;
            #pragma unroll
            for (int j = 0; j < 8; j++) {
                int n = n0 + wn + j * 8 + c_lo;
                float2 v = make_float2(acc[i][j][rr * 2], acc[i][j][rr * 2 + 1]);
                if (BIAS) {
                    float2 b2v = *(const float2*)(bias + n);
                    v.x += b2v.x; v.y += b2v.y;
                }
                if (RELU) { v.x = fmaxf(v.x, 0.f); v.y = fmaxf(v.y, 0.f); }
                if (RES) {
                    float2 r2v = *(const float2*)(rrow + n);
                    v.x += r2v.x; v.y += r2v.y;
                }
                if (OMODE == 0) {
                    *(float2*)(C + (size_t)m * N + n) = v;
                } else {
                    float s = (OMODE == 2) ? qsc : 1.0f;
                    __half2 hp = __floats2half2_rn(v.x * s, v.y * s);
                    *(__half2*)(O16 + (size_t)m * N + n) = hp;
                }
            }
        }
}

// ================= f16 mma flash attention (3-stage KV pipeline) =================
#define ATT_SMEM (112 * 1024)

__global__ __launch_bounds__(256) void attn_mma_kernel(const __half* __restrict__ qkv) {
    extern __shared__ __align__(1024) char smem[];
    int tid = threadIdx.x, lane = tid & 31, w = tid >> 5;
    int tile = blockIdx.x, h = blockIdx.y, b = blockIdx.z;
    int t0 = tile * 128;

    const __half* qb = qkv + (size_t)(b * 1024 + t0) * N_QKV + h * HEAD_SZ;
    const __half* kb = qkv + (size_t)(b * 1024) * N_QKV + 1024 + h * HEAD_SZ;
    const __half* vb = qkv + (size_t)(b * 1024) * N_QKV + 2048 + h * HEAD_SZ;

    int fr[4], fc[4];
    #pragma unroll
    for (int i = 0; i < 4; i++) {
        int flat = i * 256 + tid;
        fr[i] = flat >> 3;
        fc[i] = flat & 7;
    }

    auto issue_kv = [&](int st) {
        const __half* ks = kb + (size_t)st * 128 * N_QKV;
        const __half* vs = vb + (size_t)st * 128 * N_QKV;
        char* kd = smem + 16384 + (st % 3) * 32768;
        #pragma unroll
        for (int i = 0; i < 4; i++) {
            uint32_t sw = fr[i] * 128 + ((fc[i] ^ (fr[i] & 7)) * 16);
            size_t go = (size_t)fr[i] * N_QKV + fc[i] * 8;
            cp_async16(smem_u32(kd + sw), ks + go);
            cp_async16(smem_u32(kd + 16384 + sw), vs + go);
        }
        CP_COMMIT();
    };

    #pragma unroll
    for (int i = 0; i < 4; i++) {
        uint32_t sw = fr[i] * 128 + ((fc[i] ^ (fr[i] & 7)) * 16);
        cp_async16(smem_u32(smem + sw), qb + (size_t)fr[i] * N_QKV + fc[i] * 8);
    }
    issue_kv(0);
    issue_kv(1);

    uint32_t qa[4][4];
    float m1 = -INFINITY, m2 = -INFINITY, l1 = 0.f, l2 = 0.f;
    float oacc[8][4];
    #pragma unroll
    for (int j = 0; j < 8; j++)
        #pragma unroll
        for (int r = 0; r < 4; r++) oacc[j][r] = 0.f;

    for (int kt = 0; kt < 8; kt++) {
        if (kt < 7) asm volatile("cp.async.wait_group 1;" ::: "memory");
        else        asm volatile("cp.async.wait_group 0;" ::: "memory");
        __syncthreads();
        if (kt + 2 < 8) issue_kv(kt + 2);

        if (kt == 0) {
            uint32_t qbase = smem_u32(smem);
            #pragma unroll
            for (int kk = 0; kk < 4; kk++) {
                int arow = w * 16 + (lane & 15);
                uint32_t off = arow * 128 + (((kk * 2 + (lane >> 4)) ^ (arow & 7)) * 16);
                ldsm4(qa[kk][0], qa[kk][1], qa[kk][2], qa[kk][3], qbase + off);
            }
        }

        uint32_t kbase = smem_u32(smem + 16384 + (kt % 3) * 32768);
        uint32_t vbase = kbase + 16384;

        float sacc[16][4];
        #pragma unroll
        for (int j = 0; j < 16; j++)
            #pragma unroll
            for (int r = 0; r < 4; r++) sacc[j][r] = 0.f;

        #pragma unroll
        for (int kk = 0; kk < 4; kk++) {
            #pragma unroll
            for (int jp = 0; jp < 8; jp++) {
                int brow = (jp * 2 + (lane >> 4)) * 8 + (lane & 7);
                int sub = (lane >> 3) & 1;
                uint32_t off = brow * 128 + (((kk * 2 + sub) ^ (brow & 7)) * 16);
                uint32_t bb[4];
                ldsm4(bb[0], bb[1], bb[2], bb[3], kbase + off);
                mma_f16(sacc[jp * 2], qa[kk], bb);
                mma_f16(sacc[jp * 2 + 1], qa[kk], bb + 2);
            }
        }

        float mt1 = -INFINITY, mt2 = -INFINITY;
        #pragma unroll
        for (int j = 0; j < 16; j++) {
            mt1 = fmaxf(mt1, fmaxf(sacc[j][0], sacc[j][1]));
            mt2 = fmaxf(mt2, fmaxf(sacc[j][2], sacc[j][3]));
        }
        mt1 = fmaxf(mt1, __shfl_xor_sync(0xffffffffu, mt1, 1));
        mt1 = fmaxf(mt1, __shfl_xor_sync(0xffffffffu, mt1, 2));
        mt2 = fmaxf(mt2, __shfl_xor_sync(0xffffffffu, mt2, 1));
        mt2 = fmaxf(mt2, __shfl_xor_sync(0xffffffffu, mt2, 2));
        float mn1 = fmaxf(m1, mt1), mn2 = fmaxf(m2, mt2);
        float al1 = ex2f(m1 - mn1), al2 = ex2f(m2 - mn2);
        m1 = mn1; m2 = mn2;

        uint32_t ph[16], ph2[16];
        float ls1 = 0.f, ls2 = 0.f;
        #pragma unroll
        for (int j = 0; j < 16; j++) {
            float p0 = ex2f(sacc[j][0] - mn1);
            float p1 = ex2f(sacc[j][1] - mn1);
            float p2 = ex2f(sacc[j][2] - mn2);
            float p3 = ex2f(sacc[j][3] - mn2);
            ls1 += p0 + p1;
            ls2 += p2 + p3;
            ph[j]  = pack_h2(p0, p1);
            ph2[j] = pack_h2(p2, p3);
        }
        l1 = l1 * al1 + ls1;
        l2 = l2 * al2 + ls2;
        #pragma unroll
        for (int j = 0; j < 8; j++) {
            oacc[j][0] *= al1; oacc[j][1] *= al1;
            oacc[j][2] *= al2; oacc[j][3] *= al2;
        }

        #pragma unroll
        for (int kk2 = 0; kk2 < 8; kk2++) {
            uint32_t pa[4] = {ph[kk2 * 2], ph2[kk2 * 2], ph[kk2 * 2 + 1], ph2[kk2 * 2 + 1]};
            #pragma unroll
            for (int jp2 = 0; jp2 < 4; jp2++) {
                int srow = kk2 * 16 + ((lane >> 3) & 1) * 8 + (lane & 7);
                int ch = jp2 * 2 + (lane >> 4);
                uint32_t off = srow * 128 + ((ch ^ (srow & 7)) * 16);
                uint32_t bb[4];
                ldsm4t(bb[0], bb[1], bb[2], bb[3], vbase + off);
                mma_f16(oacc[jp2 * 2], pa, bb);
                mma_f16(oacc[jp2 * 2 + 1], pa, bb + 2);
            }
        }
    }

    l1 += __shfl_xor_sync(0xffffffffu, l1, 1);
    l1 += __shfl_xor_sync(0xffffffffu, l1, 2);
    l2 += __shfl_xor_sync(0xffffffffu, l2, 1);
    l2 += __shfl_xor_sync(0xffffffffu, l2, 2);
    float inv1 = 1.0f / l1, inv2 = 1.0f / l2;

    int r1 = t0 + w * 16 + (lane >> 2);
    int r2 = r1 + 8;
    size_t row1 = (size_t)(b * 1024 + r1) * EMB + h * HEAD_SZ;
    size_t row2 = (size_t)(b * 1024 + r2) * EMB + h * HEAD_SZ;
    #pragma unroll
    for (int j = 0; j < 8; j++) {
        int d = j * 8 + (lane & 3) * 2;
        __half2 p1v = __floats2half2_rn(oacc[j][0] * inv1, oacc[j][1] * inv1);
        __half2 p2v = __floats2half2_rn(oacc[j][2] * inv2, oacc[j][3] * inv2);
        *(__half2*)(g_a16 + row1 + d) = p1v;
        *(__half2*)(g_a16 + row2 + d) = p2v;
    }
}

// ================= launch =================
extern "C" void kernel_launch(void* const* d_in, const int* in_sizes, int n_in,
                              void* d_out, int out_size) {
    const float* x      = (const float*)d_in[0];
    const float* wq     = (const float*)d_in[1];
    const float* wk     = (const float*)d_in[2];
    const float* wv     = (const float*)d_in[3];
    const float* w_proj = (const float*)d_in[4];
    const float* b_proj = (const float*)d_in[5];
    const float* w1     = (const float*)d_in[6];
    const float* b1     = (const float*)d_in[7];
    const float* w2     = (const float*)d_in[8];
    const float* b2     = (const float*)d_in[9];
    const float* g1     = (const float*)d_in[10];
    const float* be1    = (const float*)d_in[11];
    const float* g2     = (const float*)d_in[12];
    const float* be2    = (const float*)d_in[13];
    float* out = (float*)d_out;

    float* px1;
    __half *pq16, *pa16, *pu16, *pwqkv, *pwp, *pw1, *pw2;
    cudaGetSymbolAddress((void**)&pq16,  g_qkv16);
    cudaGetSymbolAddress((void**)&pa16,  g_a16);
    cudaGetSymbolAddress((void**)&pu16,  g_u16);
    cudaGetSymbolAddress((void**)&px1,   g_x1);
    cudaGetSymbolAddress((void**)&pwqkv, g_wqkv16);
    cudaGetSymbolAddress((void**)&pwp,   g_wp16);
    cudaGetSymbolAddress((void**)&pw1,   g_w116);
    cudaGetSymbolAddress((void**)&pw2,   g_w216);

    cudaFuncSetAttribute(gemm_mma_kernel<false, false, false, 2>,
                         cudaFuncAttributeMaxDynamicSharedMemorySize, G_SMEM);
    cudaFuncSetAttribute(gemm_mma_kernel<true, false, true, 0>,
                         cudaFuncAttributeMaxDynamicSharedMemorySize, G_SMEM);
    cudaFuncSetAttribute(gemm_mma_kernel<true, true, false, 1>,
                         cudaFuncAttributeMaxDynamicSharedMemorySize, G_SMEM);
    cudaFuncSetAttribute(attn_mma_kernel,
                         cudaFuncAttributeMaxDynamicSharedMemorySize, ATT_SMEM);

    dim3 tb(32, 8);
    // --- weight prep ---
    pack_qkv_tiled<<<dim3(EMB / 32, HEAD_SZ / 32, 48), tb>>>(wq, wk, wv);
    tconv_w_tiled<<<dim3(EMB / 32, EMB / 32), tb>>>(w_proj, pwp, EMB, EMB);
    tconv_w_tiled<<<dim3(FFD / 32, EMB / 32), tb>>>(w1, pw1, EMB, FFD);
    tconv_w_tiled<<<dim3(EMB / 32, FFD / 32), tb>>>(w2, pw2, FFD, EMB);

    // --- h = LN1(x) -> f16 ---
    ln_f16_kernel<<<BT, 256>>>(x, g1, be1, pa16);
    // --- qkv = h @ Wqkv (f16 out, q pre-scaled) ---
    gemm_mma_kernel<false, false, false, 2><<<dim3(N_QKV / 256, BT / 128), 256, G_SMEM>>>(
        pa16, pwqkv, nullptr, nullptr, nullptr, pq16, BT, N_QKV, EMB);
    // --- attention (writes f16 o to a16) ---
    attn_mma_kernel<<<dim3(8, HEADS, 4), 256, ATT_SMEM>>>(pq16);
    // --- x1 = x + o @ Wproj + b_proj (fp32) ---
    gemm_mma_kernel<true, false, true, 0><<<dim3(EMB / 256, BT / 128), 256, G_SMEM>>>(
        pa16, pwp, b_proj, x, px1, nullptr, BT, EMB, EMB);
    // --- t2 = LN(LN(x1)) -> f16 (fused double-LN) ---
    ln2_f16_kernel<<<BT, 256>>>(px1, g2, be2, pa16);
    // --- u = relu(t2 @ W1 + b1) -> f16 ---
    gemm_mma_kernel<true, true, false, 1><<<dim3(FFD / 256, BT / 128), 256, G_SMEM>>>(
        pa16, pw1, b1, nullptr, nullptr, pu16, BT, FFD, EMB);
    // --- out = x1 + u @ W2 + b2 (fp32) ---
    gemm_mma_kernel<true, false, true, 0><<<dim3(EMB / 256, BT / 128), 256, G_SMEM>>>(
        pu16, pw2, b2, px1, out, nullptr, BT, EMB, FFD);
}